// round 3
// baseline (speedup 1.0000x reference)
#include <cuda_runtime.h>
#include <cstdint>

#define N_NODES 100000
#define N_EDGES 1600000
#define F_HID 128
#define F_OUT 64
#define BN_EPS 1e-5f

// ---------------- device-global scratch (no allocations allowed) ----------------
__device__ __align__(16) float g_nout[N_NODES];                 // rsqrt(max(deg_out,1))
__device__ __align__(16) float g_nin[N_NODES];                  // rsqrt(max(deg_in,1))
__device__ __align__(16) float g_agg[(size_t)N_NODES * F_HID];  // 51.2 MB scratch
__device__ __align__(16) float g_h[(size_t)N_NODES * F_HID];    // 51.2 MB layer output
__device__ __align__(16) int   g_src[N_EDGES];                  // canonical int32 indices
__device__ __align__(16) int   g_dst[N_EDGES];
__device__ __align__(16) float g_sum[F_HID];
__device__ __align__(16) float g_sumsq[F_HID];
__device__ __align__(16) float g_bna[F_HID];                    // BN scale a = g*rsqrt(var+eps)
__device__ __align__(16) float g_bnb[F_HID];                    // BN shift b = be - mean*a
__device__ int g_idx_is64;                                      // dtype flag

// ---------------- tiny init / zero kernels ----------------
__global__ void init_zero_kernel() {
    int i = blockIdx.x * blockDim.x + threadIdx.x;
    if (i < N_NODES) { g_nout[i] = 0.f; g_nin[i] = 0.f; }
    if (i < F_HID) { g_sum[i] = 0.f; g_sumsq[i] = 0.f; }
}

__global__ void zero4_kernel(float4* __restrict__ p, int n4) {
    int i = blockIdx.x * blockDim.x + threadIdx.x;
    if (i < n4) p[i] = make_float4(0.f, 0.f, 0.f, 0.f);
}

// ---------------- index dtype detection ----------------
// If indices are int64 (values < 1e5 << 2^31), every odd 32-bit word is 0.
// For genuine int32 data, P(64 sampled index words all == 0) = (1e-5)^64 ~ 0.
__global__ void detect_idx_kernel(const int* __restrict__ srcbuf) {
    if (threadIdx.x == 0) {
        int all_zero = 1;
        #pragma unroll 1
        for (int i = 0; i < 64; i++) {
            if (srcbuf[2 * i + 1] != 0) { all_zero = 0; break; }
        }
        g_idx_is64 = all_zero;
    }
}

// ---------------- convert indices to int32 + accumulate degrees ----------------
__global__ void convert_degree_kernel(const int* __restrict__ sbuf,
                                      const int* __restrict__ dbuf) {
    int e = blockIdx.x * blockDim.x + threadIdx.x;
    if (e < N_EDGES) {
        int is64 = g_idx_is64;             // uniform branch
        int s, d;
        if (is64) { s = sbuf[2 * e]; d = dbuf[2 * e]; }
        else      { s = sbuf[e];     d = dbuf[e]; }
        g_src[e] = s;
        g_dst[e] = d;
        atomicAdd(&g_nout[s], 1.f);
        atomicAdd(&g_nin[d], 1.f);
    }
}

__global__ void norm_kernel() {
    int i = blockIdx.x * blockDim.x + threadIdx.x;
    if (i < N_NODES) {
        g_nout[i] = rsqrtf(fmaxf(g_nout[i], 1.f));
        g_nin[i]  = rsqrtf(fmaxf(g_nin[i], 1.f));
    }
}

// ---------------- edge scatter: agg[dst] += f(x[src]) * n_out[src] ----------------
// One warp per edge; each lane owns 4 consecutive features (float4).
// BN=true applies fused BN+ReLU (a,b from g_bna/g_bnb) to the gathered value.
template<bool BN>
__global__ void scatter128_kernel(const float* __restrict__ x) {
    int w = (blockIdx.x * blockDim.x + threadIdx.x) >> 5;
    int lane = threadIdx.x & 31;
    if (w >= N_EDGES) return;
    int s = g_src[w];
    int d = g_dst[w];
    float sc = g_nout[s];
    float4 v = ((const float4*)x)[(size_t)s * 32 + lane];
    if (BN) {
        float4 a4 = ((const float4*)g_bna)[lane];
        float4 b4 = ((const float4*)g_bnb)[lane];
        v.x = fmaxf(fmaf(v.x, a4.x, b4.x), 0.f);
        v.y = fmaxf(fmaf(v.y, a4.y, b4.y), 0.f);
        v.z = fmaxf(fmaf(v.z, a4.z, b4.z), 0.f);
        v.w = fmaxf(fmaf(v.w, a4.w, b4.w), 0.f);
    }
    v.x *= sc; v.y *= sc; v.z *= sc; v.w *= sc;
    float* ag = g_agg + (size_t)d * 128 + lane * 4;
    atomicAdd(ag + 0, v.x);
    atomicAdd(ag + 1, v.y);
    atomicAdd(ag + 2, v.z);
    atomicAdd(ag + 3, v.w);
}

// 64-feature scatter for the final layer (y already includes n_out scaling).
__global__ void scatter64_kernel(const float* __restrict__ y,
                                 float* __restrict__ out) {
    int w = (blockIdx.x * blockDim.x + threadIdx.x) >> 5;
    int lane = threadIdx.x & 31;
    if (w >= N_EDGES) return;
    int s = g_src[w];
    int d = g_dst[w];
    float2 v = ((const float2*)y)[(size_t)s * 32 + lane];
    float* o = out + (size_t)d * 64 + lane * 2;
    atomicAdd(o + 0, v.x);
    atomicAdd(o + 1, v.y);
}

// ---------------- fused GEMM: out = f(A) @ W (+bias) with optional BN stats ----------------
// A: [M,128] row-major, W: [128,NCOL] row-major. Tile: 64 rows x NCOL cols per block.
// PRE_NIN : multiply A rows by g_nin[row] during load (conv dst-side norm)
// PRE_BN  : apply relu(A*g_bna + g_bnb) during load (fused BN+ReLU on inputs)
// STATS   : accumulate column sum / sumsq of the output h into g_sum/g_sumsq
// OUT_NOUT: multiply output rows by g_nout[row] (pre-scaling for next scatter)
// BIAS    : add bias per column
template<int NCOL, bool PRE_NIN, bool PRE_BN, bool STATS, bool OUT_NOUT, bool BIAS>
__global__ __launch_bounds__(256)
void gemm_kernel(const float* __restrict__ A,
                 const float* __restrict__ W,
                 const float* __restrict__ bias,
                 float* __restrict__ out) {
    constexpr int COLV = NCOL / 4;      // float4 columns
    constexpr int TYC  = 256 / COLV;    // threads along rows
    constexpr int RPT  = 64 / TYC;      // rows per thread

    extern __shared__ float4 smem4[];
    float4* As = smem4;                 // 64 x 32 float4  (32 KB)
    float4* Ws = As + 64 * 32;          // 128 x COLV float4
    float*  red = (float*)(Ws + 128 * COLV); // 2 * TYC * NCOL floats (stats)

    int tid = threadIdx.x;
    int rowBase = blockIdx.x * 64;

    // stage W
    for (int i = tid; i < 128 * COLV; i += 256)
        Ws[i] = ((const float4*)W)[i];

    // stage A with fused per-row / per-feature transforms
    #pragma unroll
    for (int i = 0; i < 8; i++) {
        int slot = tid + i * 256;
        int lrow = slot >> 5;
        int kk = slot & 31;
        int grow = rowBase + lrow;
        float4 v = make_float4(0.f, 0.f, 0.f, 0.f);
        if (grow < N_NODES) {
            v = ((const float4*)A)[(size_t)grow * 32 + kk];
            if (PRE_BN) {
                float4 a4 = ((const float4*)g_bna)[kk];
                float4 b4 = ((const float4*)g_bnb)[kk];
                v.x = fmaxf(fmaf(v.x, a4.x, b4.x), 0.f);
                v.y = fmaxf(fmaf(v.y, a4.y, b4.y), 0.f);
                v.z = fmaxf(fmaf(v.z, a4.z, b4.z), 0.f);
                v.w = fmaxf(fmaf(v.w, a4.w, b4.w), 0.f);
            }
            if (PRE_NIN) {
                float s = g_nin[grow];
                v.x *= s; v.y *= s; v.z *= s; v.w *= s;
            }
        }
        As[slot] = v;
    }
    __syncthreads();

    int tx = tid % COLV;
    int ty = tid / COLV;

    float4 acc[RPT];
    #pragma unroll
    for (int r = 0; r < RPT; r++) acc[r] = make_float4(0.f, 0.f, 0.f, 0.f);

    #pragma unroll 8
    for (int k4 = 0; k4 < 32; k4++) {
        float4 w0 = Ws[(k4 * 4 + 0) * COLV + tx];
        float4 w1 = Ws[(k4 * 4 + 1) * COLV + tx];
        float4 w2 = Ws[(k4 * 4 + 2) * COLV + tx];
        float4 w3 = Ws[(k4 * 4 + 3) * COLV + tx];
        #pragma unroll
        for (int r = 0; r < RPT; r++) {
            float4 av = As[(ty + r * TYC) * 32 + k4];
            acc[r].x += av.x * w0.x + av.y * w1.x + av.z * w2.x + av.w * w3.x;
            acc[r].y += av.x * w0.y + av.y * w1.y + av.z * w2.y + av.w * w3.y;
            acc[r].z += av.x * w0.z + av.y * w1.z + av.z * w2.z + av.w * w3.z;
            acc[r].w += av.x * w0.w + av.y * w1.w + av.z * w2.w + av.w * w3.w;
        }
    }

    float4 b4 = make_float4(0.f, 0.f, 0.f, 0.f);
    if (BIAS) b4 = ((const float4*)bias)[tx];

    float4 csum = make_float4(0.f, 0.f, 0.f, 0.f);
    float4 csq  = make_float4(0.f, 0.f, 0.f, 0.f);

    #pragma unroll
    for (int r = 0; r < RPT; r++) {
        int grow = rowBase + ty + r * TYC;
        if (grow < N_NODES) {
            float4 h = acc[r];
            if (BIAS) { h.x += b4.x; h.y += b4.y; h.z += b4.z; h.w += b4.w; }
            if (OUT_NOUT) {
                float s = g_nout[grow];
                h.x *= s; h.y *= s; h.z *= s; h.w *= s;
            }
            ((float4*)out)[(size_t)grow * COLV + tx] = h;
            if (STATS) {
                csum.x += h.x; csum.y += h.y; csum.z += h.z; csum.w += h.w;
                csq.x += h.x * h.x; csq.y += h.y * h.y;
                csq.z += h.z * h.z; csq.w += h.w * h.w;
            }
        }
    }

    if (STATS) {
        float* redS = red;
        float* redQ = red + TYC * NCOL;
        int base = ty * NCOL + tx * 4;
        redS[base + 0] = csum.x; redS[base + 1] = csum.y;
        redS[base + 2] = csum.z; redS[base + 3] = csum.w;
        redQ[base + 0] = csq.x;  redQ[base + 1] = csq.y;
        redQ[base + 2] = csq.z;  redQ[base + 3] = csq.w;
        __syncthreads();
        if (tid < NCOL) {
            float s = 0.f, q = 0.f;
            #pragma unroll
            for (int t = 0; t < TYC; t++) {
                s += redS[t * NCOL + tid];
                q += redQ[t * NCOL + tid];
            }
            atomicAdd(&g_sum[tid], s);
            atomicAdd(&g_sumsq[tid], q);
        }
    }
}

// ---------------- BN finalize: derive (a,b), reset accumulators ----------------
__global__ void bn_finalize_kernel(const float* __restrict__ gamma,
                                   const float* __restrict__ beta) {
    int t = threadIdx.x;
    if (t < F_HID) {
        float mean = g_sum[t] / (float)N_NODES;
        float var = g_sumsq[t] / (float)N_NODES - mean * mean;
        float a = gamma[t] * rsqrtf(var + BN_EPS);
        g_bna[t] = a;
        g_bnb[t] = fmaf(-mean, a, beta[t]);
        g_sum[t] = 0.f;
        g_sumsq[t] = 0.f;
    }
}

// ---------------- output finalize: out = out * n_in[node] + b3 ----------------
__global__ void out_finalize_kernel(float4* __restrict__ out,
                                    const float* __restrict__ b3) {
    int i = blockIdx.x * blockDim.x + threadIdx.x;   // over N_NODES*16 float4
    if (i < N_NODES * 16) {
        int node = i >> 4;
        int f4 = i & 15;
        float s = g_nin[node];
        float4 b = ((const float4*)b3)[f4];
        float4 v = out[i];
        v.x = fmaf(v.x, s, b.x);
        v.y = fmaf(v.y, s, b.y);
        v.z = fmaf(v.z, s, b.z);
        v.w = fmaf(v.w, s, b.w);
        out[i] = v;
    }
}

// ---------------- host launcher ----------------
extern "C" void kernel_launch(void* const* d_in, const int* in_sizes, int n_in,
                              void* d_out, int out_size) {
    const float* features = (const float*)d_in[0];
    const int*   srcbuf   = (const int*)d_in[1];   // int32 or int64 (detected on device)
    const int*   dstbuf   = (const int*)d_in[2];
    const float* W1  = (const float*)d_in[3];
    const float* b1  = (const float*)d_in[4];
    const float* ga1 = (const float*)d_in[5];
    const float* be1 = (const float*)d_in[6];
    const float* W2  = (const float*)d_in[7];
    const float* b2  = (const float*)d_in[8];
    const float* ga2 = (const float*)d_in[9];
    const float* be2 = (const float*)d_in[10];
    const float* W3  = (const float*)d_in[11];
    const float* b3  = (const float*)d_in[12];
    float* out = (float*)d_out;

    void* p;
    cudaGetSymbolAddress(&p, g_agg);
    float* p_agg = (float*)p;
    cudaGetSymbolAddress(&p, g_h);
    float* p_h = (float*)p;

    constexpr int SM128 = 64 * 32 * 16 + 128 * 32 * 16 + 2 * 8 * 128 * 4;   // 106496
    constexpr int SM64  = 64 * 32 * 16 + 128 * 16 * 16 + 2 * 16 * 64 * 4;   // 73728

    cudaFuncSetAttribute(gemm_kernel<128, true, false, true, false, true>,
                         cudaFuncAttributeMaxDynamicSharedMemorySize, SM128);
    cudaFuncSetAttribute(gemm_kernel<64, false, true, false, true, false>,
                         cudaFuncAttributeMaxDynamicSharedMemorySize, SM64);

    int nblk = (N_NODES + 255) / 256;
    int eblk = (N_EDGES + 255) / 256;
    int sblk = (N_EDGES + 7) / 8;        // warp per edge, 8 edges/block
    int gblk = (N_NODES + 63) / 64;

    // dtype detect + degrees + norms + zero scratch
    init_zero_kernel<<<nblk, 256>>>();
    zero4_kernel<<<(N_NODES * 32 + 255) / 256, 256>>>((float4*)p_agg, N_NODES * 32);
    detect_idx_kernel<<<1, 32>>>(srcbuf);
    convert_degree_kernel<<<eblk, 256>>>(srcbuf, dstbuf);
    norm_kernel<<<nblk, 256>>>();

    // ---- layer 1 ----
    scatter128_kernel<false><<<sblk, 256>>>(features);
    gemm_kernel<128, true, false, true, false, true>
        <<<gblk, 256, SM128>>>(p_agg, W1, b1, p_h);
    bn_finalize_kernel<<<1, 128>>>(ga1, be1);

    // ---- layer 2 (BN+ReLU of h1 fused into gather) ----
    zero4_kernel<<<(N_NODES * 32 + 255) / 256, 256>>>((float4*)p_agg, N_NODES * 32);
    scatter128_kernel<true><<<sblk, 256>>>(p_h);
    gemm_kernel<128, true, false, true, false, true>
        <<<gblk, 256, SM128>>>(p_agg, W2, b2, p_h);
    bn_finalize_kernel<<<1, 128>>>(ga2, be2);

    // ---- layer 3: GEMM first (aggregation commutes with W3), scatter 64 feats ----
    gemm_kernel<64, false, true, false, true, false>
        <<<gblk, 256, SM64>>>(p_h, W3, nullptr, p_agg);
    zero4_kernel<<<(N_NODES * 16 + 255) / 256, 256>>>((float4*)d_out, N_NODES * 16);
    scatter64_kernel<<<sblk, 256>>>(p_agg, out);
    out_finalize_kernel<<<(N_NODES * 16 + 255) / 256, 256>>>((float4*)d_out, b3);
}

// round 4
// speedup vs baseline: 1.9884x; 1.9884x over previous
#include <cuda_runtime.h>
#include <cstdint>

#define N_NODES 100000
#define N_EDGES 1600000
#define F_HID 128
#define F_OUT 64
#define BN_EPS 1e-5f

// ---------------- device-global scratch (no allocations allowed) ----------------
__device__ __align__(16) float g_nout[N_NODES];                 // rsqrt(max(deg_out,1))
__device__ __align__(16) float g_nin[N_NODES];                  // rsqrt(max(deg_in,1))
__device__ __align__(16) float g_agg[(size_t)N_NODES * F_HID];  // 51.2 MB buffer A
__device__ __align__(16) float g_h[(size_t)N_NODES * F_HID];    // 51.2 MB buffer B
__device__ __align__(16) int   g_src[N_EDGES];                  // canonical int32 indices
__device__ __align__(16) int   g_dst[N_EDGES];
__device__ __align__(16) int   g_csr_src[N_EDGES];              // src ids bucketed by dst
__device__ __align__(16) int   g_row_ptr[N_NODES + 1];
__device__ __align__(16) int   g_cursor[N_NODES];
__device__ __align__(16) int   g_deg_out[N_NODES];
__device__ __align__(16) int   g_deg_in[N_NODES];
__device__ __align__(16) float g_sum[F_HID];
__device__ __align__(16) float g_sumsq[F_HID];
__device__ __align__(16) float g_bna[F_HID];                    // BN scale a = g*rsqrt(var+eps)
__device__ __align__(16) float g_bnb[F_HID];                    // BN shift b = be - mean*a
__device__ int g_idx_is64;                                      // dtype flag

// ---------------- init ----------------
__global__ void init_zero_kernel() {
    int i = blockIdx.x * blockDim.x + threadIdx.x;
    if (i < N_NODES) { g_deg_out[i] = 0; g_deg_in[i] = 0; }
    if (i < F_HID) { g_sum[i] = 0.f; g_sumsq[i] = 0.f; }
}

// ---------------- index dtype detection ----------------
// If indices are int64 (values < 1e5 << 2^31), every odd 32-bit word is 0.
// For genuine int32 data, P(64 sampled index words all == 0) = (1e-5)^64 ~ 0.
__global__ void detect_idx_kernel(const int* __restrict__ srcbuf) {
    if (threadIdx.x == 0) {
        int all_zero = 1;
        #pragma unroll 1
        for (int i = 0; i < 64; i++) {
            if (srcbuf[2 * i + 1] != 0) { all_zero = 0; break; }
        }
        g_idx_is64 = all_zero;
    }
}

// ---------------- convert indices + int degree histogram ----------------
__global__ void convert_degree_kernel(const int* __restrict__ sbuf,
                                      const int* __restrict__ dbuf) {
    int e = blockIdx.x * blockDim.x + threadIdx.x;
    if (e < N_EDGES) {
        int is64 = g_idx_is64;             // uniform branch
        int s, d;
        if (is64) { s = sbuf[2 * e]; d = dbuf[2 * e]; }
        else      { s = sbuf[e];     d = dbuf[e]; }
        g_src[e] = s;
        g_dst[e] = d;
        atomicAdd(&g_deg_out[s], 1);
        atomicAdd(&g_deg_in[d], 1);
    }
}

// ---------------- exclusive scan of deg_in -> row_ptr (single block) ----------------
__global__ void scan_kernel() {
    __shared__ int wsum[32];
    __shared__ int chunk_total;
    __shared__ int running_s;
    int tid = threadIdx.x, lane = tid & 31, wid = tid >> 5;
    if (tid == 0) running_s = 0;
    __syncthreads();
    for (int base = 0; base < N_NODES; base += 1024) {
        int i = base + tid;
        int v = (i < N_NODES) ? g_deg_in[i] : 0;
        int incl = v;
        #pragma unroll
        for (int off = 1; off < 32; off <<= 1) {
            int t = __shfl_up_sync(0xffffffffu, incl, off);
            if (lane >= off) incl += t;
        }
        if (lane == 31) wsum[wid] = incl;
        __syncthreads();
        if (wid == 0) {
            int wv = wsum[lane];
            int winc = wv;
            #pragma unroll
            for (int off = 1; off < 32; off <<= 1) {
                int t = __shfl_up_sync(0xffffffffu, winc, off);
                if (lane >= off) winc += t;
            }
            wsum[lane] = winc - wv;             // exclusive within chunk
            if (lane == 31) chunk_total = winc; // chunk sum
        }
        __syncthreads();
        int excl = running_s + wsum[wid] + incl - v;
        if (i < N_NODES) { g_row_ptr[i] = excl; g_cursor[i] = excl; }
        __syncthreads();
        if (tid == 0) running_s += chunk_total;
        __syncthreads();
    }
    if (threadIdx.x == 0) g_row_ptr[N_NODES] = running_s;
}

// ---------------- norms from int degrees ----------------
__global__ void norm_kernel() {
    int i = blockIdx.x * blockDim.x + threadIdx.x;
    if (i < N_NODES) {
        g_nout[i] = rsqrtf(fmaxf((float)g_deg_out[i], 1.f));
        g_nin[i]  = rsqrtf(fmaxf((float)g_deg_in[i], 1.f));
    }
}

// ---------------- bucket fill: csr_src[row_ptr[dst] + k] = src ----------------
__global__ void fill_csr_kernel() {
    int e = blockIdx.x * blockDim.x + threadIdx.x;
    if (e < N_EDGES) {
        int d = g_dst[e];
        int pos = atomicAdd(&g_cursor[d], 1);
        g_csr_src[pos] = g_src[e];
    }
}

// ---------------- prep passes: build z (pre-scaled gather source) ----------------
// layer 1: z = features * n_out[node]
__global__ void prep1_kernel(const float4* __restrict__ x, float4* __restrict__ z) {
    int i = blockIdx.x * blockDim.x + threadIdx.x;   // over N*32 float4
    if (i < N_NODES * 32) {
        float s = g_nout[i >> 5];
        float4 v = x[i];
        v.x *= s; v.y *= s; v.z *= s; v.w *= s;
        z[i] = v;
    }
}
// layer 2: z = relu(h*a + b) * n_out[node]
__global__ void prep2_kernel(const float4* __restrict__ h, float4* __restrict__ z) {
    int i = blockIdx.x * blockDim.x + threadIdx.x;
    if (i < N_NODES * 32) {
        int k = i & 31;
        float s = g_nout[i >> 5];
        float4 v = h[i];
        float4 a4 = ((const float4*)g_bna)[k];
        float4 b4 = ((const float4*)g_bnb)[k];
        v.x = fmaxf(fmaf(v.x, a4.x, b4.x), 0.f) * s;
        v.y = fmaxf(fmaf(v.y, a4.y, b4.y), 0.f) * s;
        v.z = fmaxf(fmaf(v.z, a4.z, b4.z), 0.f) * s;
        v.w = fmaxf(fmaf(v.w, a4.w, b4.w), 0.f) * s;
        z[i] = v;
    }
}

// ---------------- fused CSR-gather + GEMM (128 -> 128) ----------------
// Block = 64 dst rows. Warp w gathers rows w, w+8, ... : acc = n_in[d] * sum_e z[src_e]
// staged into smem, then 64x128x128 GEMM with bias + BN-stats epilogue.
__global__ __launch_bounds__(256)
void fused_conv_kernel(const float* __restrict__ z,
                       const float* __restrict__ W,
                       const float* __restrict__ bias,
                       float* __restrict__ out) {
    extern __shared__ float4 smem4[];
    float4* As = smem4;                 // 64 x 32 float4 (32 KB)
    float4* Ws = As + 64 * 32;          // 128 x 32 float4 (64 KB)
    float*  red = (float*)(Ws + 128 * 32); // 2 * 8 * 128 floats (8 KB)

    int tid = threadIdx.x;
    int lane = tid & 31;
    int wid = tid >> 5;
    int rowBase = blockIdx.x * 64;
    const float4* x4 = (const float4*)z;

    // stage W
    for (int i = tid; i < 128 * 32; i += 256)
        Ws[i] = ((const float4*)W)[i];

    // gather phase: one warp per row, unroll-4 for MLP
    for (int r = wid; r < 64; r += 8) {
        int grow = rowBase + r;
        float4 acc = make_float4(0.f, 0.f, 0.f, 0.f);
        if (grow < N_NODES) {
            int beg = g_row_ptr[grow];
            int end = g_row_ptr[grow + 1];
            int j = beg;
            for (; j + 4 <= end; j += 4) {
                int s0 = g_csr_src[j + 0];
                int s1 = g_csr_src[j + 1];
                int s2 = g_csr_src[j + 2];
                int s3 = g_csr_src[j + 3];
                float4 v0 = x4[(size_t)s0 * 32 + lane];
                float4 v1 = x4[(size_t)s1 * 32 + lane];
                float4 v2 = x4[(size_t)s2 * 32 + lane];
                float4 v3 = x4[(size_t)s3 * 32 + lane];
                acc.x += (v0.x + v1.x) + (v2.x + v3.x);
                acc.y += (v0.y + v1.y) + (v2.y + v3.y);
                acc.z += (v0.z + v1.z) + (v2.z + v3.z);
                acc.w += (v0.w + v1.w) + (v2.w + v3.w);
            }
            for (; j < end; j++) {
                int s = g_csr_src[j];
                float4 v = x4[(size_t)s * 32 + lane];
                acc.x += v.x; acc.y += v.y; acc.z += v.z; acc.w += v.w;
            }
            float ni = g_nin[grow];
            acc.x *= ni; acc.y *= ni; acc.z *= ni; acc.w *= ni;
        }
        As[r * 32 + lane] = acc;
    }
    __syncthreads();

    // GEMM phase: COLV=32 float4 cols, TYC=8, RPT=8
    int tx = tid & 31;       // float4 column
    int ty = tid >> 5;       // row group

    float4 acc[8];
    #pragma unroll
    for (int r = 0; r < 8; r++) acc[r] = make_float4(0.f, 0.f, 0.f, 0.f);

    #pragma unroll 8
    for (int k4 = 0; k4 < 32; k4++) {
        float4 w0 = Ws[(k4 * 4 + 0) * 32 + tx];
        float4 w1 = Ws[(k4 * 4 + 1) * 32 + tx];
        float4 w2 = Ws[(k4 * 4 + 2) * 32 + tx];
        float4 w3 = Ws[(k4 * 4 + 3) * 32 + tx];
        #pragma unroll
        for (int r = 0; r < 8; r++) {
            float4 av = As[(ty + r * 8) * 32 + k4];
            acc[r].x += av.x * w0.x + av.y * w1.x + av.z * w2.x + av.w * w3.x;
            acc[r].y += av.x * w0.y + av.y * w1.y + av.z * w2.y + av.w * w3.y;
            acc[r].z += av.x * w0.z + av.y * w1.z + av.z * w2.z + av.w * w3.z;
            acc[r].w += av.x * w0.w + av.y * w1.w + av.z * w2.w + av.w * w3.w;
        }
    }

    float4 b4 = ((const float4*)bias)[tx];
    float4 csum = make_float4(0.f, 0.f, 0.f, 0.f);
    float4 csq  = make_float4(0.f, 0.f, 0.f, 0.f);

    #pragma unroll
    for (int r = 0; r < 8; r++) {
        int grow = rowBase + ty + r * 8;
        if (grow < N_NODES) {
            float4 h = acc[r];
            h.x += b4.x; h.y += b4.y; h.z += b4.z; h.w += b4.w;
            ((float4*)out)[(size_t)grow * 32 + tx] = h;
            csum.x += h.x; csum.y += h.y; csum.z += h.z; csum.w += h.w;
            csq.x += h.x * h.x; csq.y += h.y * h.y;
            csq.z += h.z * h.z; csq.w += h.w * h.w;
        }
    }

    // BN stats reduction
    float* redS = red;
    float* redQ = red + 8 * 128;
    int base = ty * 128 + tx * 4;
    redS[base + 0] = csum.x; redS[base + 1] = csum.y;
    redS[base + 2] = csum.z; redS[base + 3] = csum.w;
    redQ[base + 0] = csq.x;  redQ[base + 1] = csq.y;
    redQ[base + 2] = csq.z;  redQ[base + 3] = csq.w;
    __syncthreads();
    if (tid < 128) {
        float s = 0.f, q = 0.f;
        #pragma unroll
        for (int t = 0; t < 8; t++) {
            s += redS[t * 128 + tid];
            q += redQ[t * 128 + tid];
        }
        atomicAdd(&g_sum[tid], s);
        atomicAdd(&g_sumsq[tid], q);
    }
}

// ---------------- plain GEMM for layer 3: y = relu(bn2(h2)) @ W3, scaled by n_out ----------------
__global__ __launch_bounds__(256)
void gemm64_kernel(const float* __restrict__ A,
                   const float* __restrict__ W,
                   float* __restrict__ out) {
    constexpr int COLV = 16;   // 64 cols = 16 float4
    constexpr int TYC  = 16;
    constexpr int RPT  = 4;

    extern __shared__ float4 smem4[];
    float4* As = smem4;               // 64 x 32 float4
    float4* Ws = As + 64 * 32;        // 128 x 16 float4

    int tid = threadIdx.x;
    int rowBase = blockIdx.x * 64;

    for (int i = tid; i < 128 * COLV; i += 256)
        Ws[i] = ((const float4*)W)[i];

    #pragma unroll
    for (int i = 0; i < 8; i++) {
        int slot = tid + i * 256;
        int lrow = slot >> 5;
        int kk = slot & 31;
        int grow = rowBase + lrow;
        float4 v = make_float4(0.f, 0.f, 0.f, 0.f);
        if (grow < N_NODES) {
            v = ((const float4*)A)[(size_t)grow * 32 + kk];
            float4 a4 = ((const float4*)g_bna)[kk];
            float4 b4 = ((const float4*)g_bnb)[kk];
            v.x = fmaxf(fmaf(v.x, a4.x, b4.x), 0.f);
            v.y = fmaxf(fmaf(v.y, a4.y, b4.y), 0.f);
            v.z = fmaxf(fmaf(v.z, a4.z, b4.z), 0.f);
            v.w = fmaxf(fmaf(v.w, a4.w, b4.w), 0.f);
        }
        As[slot] = v;
    }
    __syncthreads();

    int tx = tid % COLV;
    int ty = tid / COLV;

    float4 acc[RPT];
    #pragma unroll
    for (int r = 0; r < RPT; r++) acc[r] = make_float4(0.f, 0.f, 0.f, 0.f);

    #pragma unroll 8
    for (int k4 = 0; k4 < 32; k4++) {
        float4 w0 = Ws[(k4 * 4 + 0) * COLV + tx];
        float4 w1 = Ws[(k4 * 4 + 1) * COLV + tx];
        float4 w2 = Ws[(k4 * 4 + 2) * COLV + tx];
        float4 w3 = Ws[(k4 * 4 + 3) * COLV + tx];
        #pragma unroll
        for (int r = 0; r < RPT; r++) {
            float4 av = As[(ty + r * TYC) * 32 + k4];
            acc[r].x += av.x * w0.x + av.y * w1.x + av.z * w2.x + av.w * w3.x;
            acc[r].y += av.x * w0.y + av.y * w1.y + av.z * w2.y + av.w * w3.y;
            acc[r].z += av.x * w0.z + av.y * w1.z + av.z * w2.z + av.w * w3.z;
            acc[r].w += av.x * w0.w + av.y * w1.w + av.z * w2.w + av.w * w3.w;
        }
    }

    #pragma unroll
    for (int r = 0; r < RPT; r++) {
        int grow = rowBase + ty + r * TYC;
        if (grow < N_NODES) {
            float s = g_nout[grow];
            float4 h = acc[r];
            h.x *= s; h.y *= s; h.z *= s; h.w *= s;
            ((float4*)out)[(size_t)grow * COLV + tx] = h;
        }
    }
}

// ---------------- BN finalize: derive (a,b), reset accumulators ----------------
__global__ void bn_finalize_kernel(const float* __restrict__ gamma,
                                   const float* __restrict__ beta) {
    int t = threadIdx.x;
    if (t < F_HID) {
        float mean = g_sum[t] / (float)N_NODES;
        float var = g_sumsq[t] / (float)N_NODES - mean * mean;
        float a = gamma[t] * rsqrtf(var + BN_EPS);
        g_bna[t] = a;
        g_bnb[t] = fmaf(-mean, a, beta[t]);
        g_sum[t] = 0.f;
        g_sumsq[t] = 0.f;
    }
}

// ---------------- final CSR gather (64 feats): out = n_in * sum(y[src]) + b3 ----------------
__global__ void gather64_kernel(const float* __restrict__ y,
                                const float* __restrict__ b3,
                                float* __restrict__ out) {
    int w = (blockIdx.x * blockDim.x + threadIdx.x) >> 5;   // dst node
    int lane = threadIdx.x & 31;                            // owns float2
    if (w >= N_NODES) return;
    const float2* y2 = (const float2*)y;
    int beg = g_row_ptr[w];
    int end = g_row_ptr[w + 1];
    float2 acc = make_float2(0.f, 0.f);
    int j = beg;
    for (; j + 4 <= end; j += 4) {
        int s0 = g_csr_src[j + 0];
        int s1 = g_csr_src[j + 1];
        int s2 = g_csr_src[j + 2];
        int s3 = g_csr_src[j + 3];
        float2 v0 = y2[(size_t)s0 * 32 + lane];
        float2 v1 = y2[(size_t)s1 * 32 + lane];
        float2 v2 = y2[(size_t)s2 * 32 + lane];
        float2 v3 = y2[(size_t)s3 * 32 + lane];
        acc.x += (v0.x + v1.x) + (v2.x + v3.x);
        acc.y += (v0.y + v1.y) + (v2.y + v3.y);
    }
    for (; j < end; j++) {
        int s = g_csr_src[j];
        float2 v = y2[(size_t)s * 32 + lane];
        acc.x += v.x; acc.y += v.y;
    }
    float ni = g_nin[w];
    float2 b = ((const float2*)b3)[lane];
    float2 o;
    o.x = fmaf(acc.x, ni, b.x);
    o.y = fmaf(acc.y, ni, b.y);
    ((float2*)out)[(size_t)w * 32 + lane] = o;
}

// ---------------- host launcher ----------------
extern "C" void kernel_launch(void* const* d_in, const int* in_sizes, int n_in,
                              void* d_out, int out_size) {
    const float* features = (const float*)d_in[0];
    const int*   srcbuf   = (const int*)d_in[1];   // int32 or int64 (detected on device)
    const int*   dstbuf   = (const int*)d_in[2];
    const float* W1  = (const float*)d_in[3];
    const float* b1  = (const float*)d_in[4];
    const float* ga1 = (const float*)d_in[5];
    const float* be1 = (const float*)d_in[6];
    const float* W2  = (const float*)d_in[7];
    const float* b2  = (const float*)d_in[8];
    const float* ga2 = (const float*)d_in[9];
    const float* be2 = (const float*)d_in[10];
    const float* W3  = (const float*)d_in[11];
    const float* b3  = (const float*)d_in[12];
    float* out = (float*)d_out;

    void* p;
    cudaGetSymbolAddress(&p, g_agg);
    float* p_agg = (float*)p;
    cudaGetSymbolAddress(&p, g_h);
    float* p_h = (float*)p;

    constexpr int SM128 = 64 * 32 * 16 + 128 * 32 * 16 + 2 * 8 * 128 * 4;   // 106496
    constexpr int SM64  = 64 * 32 * 16 + 128 * 16 * 16;                     // 65536

    cudaFuncSetAttribute(fused_conv_kernel,
                         cudaFuncAttributeMaxDynamicSharedMemorySize, SM128);
    cudaFuncSetAttribute(gemm64_kernel,
                         cudaFuncAttributeMaxDynamicSharedMemorySize, SM64);

    int nblk = (N_NODES + 255) / 256;
    int eblk = (N_EDGES + 255) / 256;
    int gblk = (N_NODES + 63) / 64;
    int fblk = (N_NODES * 32 + 255) / 256;

    // graph preprocessing: dtype detect, degrees, row_ptr, norms, CSR fill
    init_zero_kernel<<<nblk, 256>>>();
    detect_idx_kernel<<<1, 32>>>(srcbuf);
    convert_degree_kernel<<<eblk, 256>>>(srcbuf, dstbuf);
    scan_kernel<<<1, 1024>>>();
    norm_kernel<<<nblk, 256>>>();
    fill_csr_kernel<<<eblk, 256>>>();

    // ---- layer 1 ----
    prep1_kernel<<<fblk, 256>>>((const float4*)features, (float4*)p_agg);
    fused_conv_kernel<<<gblk, 256, SM128>>>(p_agg, W1, b1, p_h);
    bn_finalize_kernel<<<1, 128>>>(ga1, be1);

    // ---- layer 2 ----
    prep2_kernel<<<fblk, 256>>>((const float4*)p_h, (float4*)p_agg);
    fused_conv_kernel<<<gblk, 256, SM128>>>(p_agg, W2, b2, p_h);
    bn_finalize_kernel<<<1, 128>>>(ga2, be2);

    // ---- layer 3: GEMM first (aggregation commutes with W3), then CSR gather ----
    gemm64_kernel<<<gblk, 256, SM64>>>(p_h, W3, p_agg);   // y = relu(bn2(h2))@W3 * n_out
    gather64_kernel<<<(N_NODES + 7) / 8, 256>>>(p_agg, b3, out);
}

// round 5
// speedup vs baseline: 2.2412x; 1.1272x over previous
#include <cuda_runtime.h>
#include <cstdint>

#define N_NODES 100000
#define N_EDGES 1600000
#define F_HID 128
#define F_OUT 64
#define BN_EPS 1e-5f
#define SCAN_BLOCKS 98            // 98 * 1024 = 100352 >= N_NODES

// ---------------- device-global scratch (no allocations allowed) ----------------
__device__ __align__(16) float g_nout[N_NODES];                 // rsqrt(max(deg_out,1))
__device__ __align__(16) float g_nin[N_NODES];                  // rsqrt(max(deg_in,1))
__device__ __align__(16) float g_agg[(size_t)N_NODES * F_HID];  // 51.2 MB buffer A
__device__ __align__(16) float g_h[(size_t)N_NODES * F_HID];    // 51.2 MB buffer B
__device__ __align__(16) int   g_src[N_EDGES];                  // canonical int32 indices
__device__ __align__(16) int   g_dst[N_EDGES];
__device__ __align__(16) int   g_csr_src[N_EDGES];              // src ids bucketed by dst
__device__ __align__(16) int   g_row_ptr[N_NODES + 1];
__device__ __align__(16) int   g_cursor[N_NODES];
__device__ __align__(16) int   g_deg_out[N_NODES];
__device__ __align__(16) int   g_deg_in[N_NODES];
__device__ __align__(16) int   g_partial[128];                  // scan block partials
__device__ __align__(16) float g_sum[F_HID];
__device__ __align__(16) float g_sumsq[F_HID];
__device__ __align__(16) float g_bna[F_HID];                    // BN scale a = g*rsqrt(var+eps)
__device__ __align__(16) float g_bnb[F_HID];                    // BN shift b = be - mean*a
__device__ int g_idx_is64;                                      // dtype flag

// ---------------- init + dtype detection ----------------
// If indices are int64 (values < 1e5 << 2^31), every odd 32-bit word is 0.
// For genuine int32 data, P(64 sampled index words all == 0) = (1e-5)^64 ~ 0.
__global__ void init_detect_kernel(const int* __restrict__ srcbuf) {
    int i = blockIdx.x * blockDim.x + threadIdx.x;
    if (i < N_NODES) { g_deg_out[i] = 0; g_deg_in[i] = 0; }
    if (i < F_HID) { g_sum[i] = 0.f; g_sumsq[i] = 0.f; }
    if (blockIdx.x == 0 && threadIdx.x == 0) {
        int all_zero = 1;
        #pragma unroll 1
        for (int k = 0; k < 64; k++) {
            if (srcbuf[2 * k + 1] != 0) { all_zero = 0; break; }
        }
        g_idx_is64 = all_zero;
    }
}

// ---------------- convert indices + int degree histogram ----------------
__global__ void convert_degree_kernel(const int* __restrict__ sbuf,
                                      const int* __restrict__ dbuf) {
    int e = blockIdx.x * blockDim.x + threadIdx.x;
    if (e < N_EDGES) {
        int is64 = g_idx_is64;             // uniform branch
        int s, d;
        if (is64) { s = sbuf[2 * e]; d = dbuf[2 * e]; }
        else      { s = sbuf[e];     d = dbuf[e]; }
        g_src[e] = s;
        g_dst[e] = d;
        atomicAdd(&g_deg_out[s], 1);
        atomicAdd(&g_deg_in[d], 1);
    }
}

// ---------------- scan pass A: per-block sums of deg_in (1024 elems/block) ----------------
__global__ __launch_bounds__(1024) void scanA_kernel() {
    __shared__ int wsum[32];
    int tid = threadIdx.x, lane = tid & 31, wid = tid >> 5;
    int i = blockIdx.x * 1024 + tid;
    int v = (i < N_NODES) ? g_deg_in[i] : 0;
    int s = v;
    #pragma unroll
    for (int off = 16; off > 0; off >>= 1)
        s += __shfl_down_sync(0xffffffffu, s, off);
    if (lane == 0) wsum[wid] = s;
    __syncthreads();
    if (wid == 0) {
        int t = wsum[lane];
        #pragma unroll
        for (int off = 16; off > 0; off >>= 1)
            t += __shfl_down_sync(0xffffffffu, t, off);
        if (lane == 0) g_partial[blockIdx.x] = t;
    }
}

// ---------------- scan pass B: block offset via partial re-reduce + local scan + norms ----------------
__global__ __launch_bounds__(1024) void scanB_kernel() {
    __shared__ int wsum[32];
    __shared__ int blockOffset;
    int tid = threadIdx.x, lane = tid & 31, wid = tid >> 5;

    // block offset = sum of partials of earlier blocks (<=97 values, trivial)
    if (wid == 0) {
        int acc = 0;
        for (int j = lane; j < blockIdx.x; j += 32) acc += g_partial[j];
        #pragma unroll
        for (int off = 16; off > 0; off >>= 1)
            acc += __shfl_down_sync(0xffffffffu, acc, off);
        if (lane == 0) blockOffset = acc;
    }

    int i = blockIdx.x * 1024 + tid;
    int v = (i < N_NODES) ? g_deg_in[i] : 0;
    int incl = v;
    #pragma unroll
    for (int off = 1; off < 32; off <<= 1) {
        int t = __shfl_up_sync(0xffffffffu, incl, off);
        if (lane >= off) incl += t;
    }
    if (lane == 31) wsum[wid] = incl;
    __syncthreads();
    if (wid == 0) {
        int wv = wsum[lane];
        int winc = wv;
        #pragma unroll
        for (int off = 1; off < 32; off <<= 1) {
            int t = __shfl_up_sync(0xffffffffu, winc, off);
            if (lane >= off) winc += t;
        }
        wsum[lane] = winc - wv;     // exclusive across warps
    }
    __syncthreads();
    int excl = blockOffset + wsum[wid] + incl - v;
    if (i < N_NODES) {
        g_row_ptr[i] = excl;
        g_cursor[i] = excl;
        g_nout[i] = rsqrtf(fmaxf((float)g_deg_out[i], 1.f));
        g_nin[i]  = rsqrtf(fmaxf((float)v, 1.f));
        if (i == N_NODES - 1) g_row_ptr[N_NODES] = excl + v;
    }
}

// ---------------- bucket fill: csr_src[row_ptr[dst] + k] = src ----------------
__global__ void fill_csr_kernel() {
    int e = blockIdx.x * blockDim.x + threadIdx.x;
    if (e < N_EDGES) {
        int d = g_dst[e];
        int pos = atomicAdd(&g_cursor[d], 1);
        g_csr_src[pos] = g_src[e];
    }
}

// ---------------- fused CSR-gather + GEMM (128 -> 128) ----------------
// Block = 64 dst rows. Warp w gathers rows w, w+8, ...
//   LAYER 1: acc = n_in[d] * sum_e x[src]*n_out[src]
//   LAYER 2: acc = n_in[d] * sum_e relu(bn(x[src]))*n_out[src]
// staged into smem, then 64x128x128 GEMM with bias + BN-stats epilogue.
template<int LAYER>
__global__ __launch_bounds__(256)
void fused_conv_kernel(const float* __restrict__ x,
                       const float* __restrict__ W,
                       const float* __restrict__ bias,
                       float* __restrict__ out) {
    extern __shared__ float4 smem4[];
    float4* As = smem4;                 // 64 x 32 float4 (32 KB)
    float4* Ws = As + 64 * 32;          // 128 x 32 float4 (64 KB)
    float*  red = (float*)(Ws + 128 * 32); // 2 * 8 * 128 floats (8 KB)

    int tid = threadIdx.x;
    int lane = tid & 31;
    int wid = tid >> 5;
    int rowBase = blockIdx.x * 64;
    const float4* x4 = (const float4*)x;

    // stage W
    for (int i = tid; i < 128 * 32; i += 256)
        Ws[i] = ((const float4*)W)[i];

    float4 a4 = make_float4(0.f, 0.f, 0.f, 0.f);
    float4 c4 = make_float4(0.f, 0.f, 0.f, 0.f);
    if (LAYER == 2) {
        a4 = ((const float4*)g_bna)[lane];
        c4 = ((const float4*)g_bnb)[lane];
    }

    // gather phase: one warp per row, unroll-4 for MLP
    for (int r = wid; r < 64; r += 8) {
        int grow = rowBase + r;
        float4 acc = make_float4(0.f, 0.f, 0.f, 0.f);
        if (grow < N_NODES) {
            int beg = g_row_ptr[grow];
            int end = g_row_ptr[grow + 1];
            int j = beg;
            for (; j + 4 <= end; j += 4) {
                int s0 = g_csr_src[j + 0];
                int s1 = g_csr_src[j + 1];
                int s2 = g_csr_src[j + 2];
                int s3 = g_csr_src[j + 3];
                float n0 = g_nout[s0], n1 = g_nout[s1];
                float n2 = g_nout[s2], n3 = g_nout[s3];
                float4 v0 = x4[(size_t)s0 * 32 + lane];
                float4 v1 = x4[(size_t)s1 * 32 + lane];
                float4 v2 = x4[(size_t)s2 * 32 + lane];
                float4 v3 = x4[(size_t)s3 * 32 + lane];
                if (LAYER == 2) {
                    v0.x = fmaxf(fmaf(v0.x, a4.x, c4.x), 0.f);
                    v0.y = fmaxf(fmaf(v0.y, a4.y, c4.y), 0.f);
                    v0.z = fmaxf(fmaf(v0.z, a4.z, c4.z), 0.f);
                    v0.w = fmaxf(fmaf(v0.w, a4.w, c4.w), 0.f);
                    v1.x = fmaxf(fmaf(v1.x, a4.x, c4.x), 0.f);
                    v1.y = fmaxf(fmaf(v1.y, a4.y, c4.y), 0.f);
                    v1.z = fmaxf(fmaf(v1.z, a4.z, c4.z), 0.f);
                    v1.w = fmaxf(fmaf(v1.w, a4.w, c4.w), 0.f);
                    v2.x = fmaxf(fmaf(v2.x, a4.x, c4.x), 0.f);
                    v2.y = fmaxf(fmaf(v2.y, a4.y, c4.y), 0.f);
                    v2.z = fmaxf(fmaf(v2.z, a4.z, c4.z), 0.f);
                    v2.w = fmaxf(fmaf(v2.w, a4.w, c4.w), 0.f);
                    v3.x = fmaxf(fmaf(v3.x, a4.x, c4.x), 0.f);
                    v3.y = fmaxf(fmaf(v3.y, a4.y, c4.y), 0.f);
                    v3.z = fmaxf(fmaf(v3.z, a4.z, c4.z), 0.f);
                    v3.w = fmaxf(fmaf(v3.w, a4.w, c4.w), 0.f);
                }
                acc.x = fmaf(v0.x, n0, acc.x); acc.y = fmaf(v0.y, n0, acc.y);
                acc.z = fmaf(v0.z, n0, acc.z); acc.w = fmaf(v0.w, n0, acc.w);
                acc.x = fmaf(v1.x, n1, acc.x); acc.y = fmaf(v1.y, n1, acc.y);
                acc.z = fmaf(v1.z, n1, acc.z); acc.w = fmaf(v1.w, n1, acc.w);
                acc.x = fmaf(v2.x, n2, acc.x); acc.y = fmaf(v2.y, n2, acc.y);
                acc.z = fmaf(v2.z, n2, acc.z); acc.w = fmaf(v2.w, n2, acc.w);
                acc.x = fmaf(v3.x, n3, acc.x); acc.y = fmaf(v3.y, n3, acc.y);
                acc.z = fmaf(v3.z, n3, acc.z); acc.w = fmaf(v3.w, n3, acc.w);
            }
            for (; j < end; j++) {
                int s = g_csr_src[j];
                float n = g_nout[s];
                float4 v = x4[(size_t)s * 32 + lane];
                if (LAYER == 2) {
                    v.x = fmaxf(fmaf(v.x, a4.x, c4.x), 0.f);
                    v.y = fmaxf(fmaf(v.y, a4.y, c4.y), 0.f);
                    v.z = fmaxf(fmaf(v.z, a4.z, c4.z), 0.f);
                    v.w = fmaxf(fmaf(v.w, a4.w, c4.w), 0.f);
                }
                acc.x = fmaf(v.x, n, acc.x); acc.y = fmaf(v.y, n, acc.y);
                acc.z = fmaf(v.z, n, acc.z); acc.w = fmaf(v.w, n, acc.w);
            }
            float ni = g_nin[grow];
            acc.x *= ni; acc.y *= ni; acc.z *= ni; acc.w *= ni;
        }
        As[r * 32 + lane] = acc;
    }
    __syncthreads();

    // GEMM phase: COLV=32 float4 cols, TYC=8, RPT=8
    int tx = tid & 31;       // float4 column
    int ty = tid >> 5;       // row group

    float4 acc[8];
    #pragma unroll
    for (int r = 0; r < 8; r++) acc[r] = make_float4(0.f, 0.f, 0.f, 0.f);

    #pragma unroll 8
    for (int k4 = 0; k4 < 32; k4++) {
        float4 w0 = Ws[(k4 * 4 + 0) * 32 + tx];
        float4 w1 = Ws[(k4 * 4 + 1) * 32 + tx];
        float4 w2 = Ws[(k4 * 4 + 2) * 32 + tx];
        float4 w3 = Ws[(k4 * 4 + 3) * 32 + tx];
        #pragma unroll
        for (int r = 0; r < 8; r++) {
            float4 av = As[(ty + r * 8) * 32 + k4];
            acc[r].x += av.x * w0.x + av.y * w1.x + av.z * w2.x + av.w * w3.x;
            acc[r].y += av.x * w0.y + av.y * w1.y + av.z * w2.y + av.w * w3.y;
            acc[r].z += av.x * w0.z + av.y * w1.z + av.z * w2.z + av.w * w3.z;
            acc[r].w += av.x * w0.w + av.y * w1.w + av.z * w2.w + av.w * w3.w;
        }
    }

    float4 b4 = ((const float4*)bias)[tx];
    float4 csum = make_float4(0.f, 0.f, 0.f, 0.f);
    float4 csq  = make_float4(0.f, 0.f, 0.f, 0.f);

    #pragma unroll
    for (int r = 0; r < 8; r++) {
        int grow = rowBase + ty + r * 8;
        if (grow < N_NODES) {
            float4 h = acc[r];
            h.x += b4.x; h.y += b4.y; h.z += b4.z; h.w += b4.w;
            ((float4*)out)[(size_t)grow * 32 + tx] = h;
            csum.x += h.x; csum.y += h.y; csum.z += h.z; csum.w += h.w;
            csq.x += h.x * h.x; csq.y += h.y * h.y;
            csq.z += h.z * h.z; csq.w += h.w * h.w;
        }
    }

    // BN stats reduction
    float* redS = red;
    float* redQ = red + 8 * 128;
    int base = ty * 128 + tx * 4;
    redS[base + 0] = csum.x; redS[base + 1] = csum.y;
    redS[base + 2] = csum.z; redS[base + 3] = csum.w;
    redQ[base + 0] = csq.x;  redQ[base + 1] = csq.y;
    redQ[base + 2] = csq.z;  redQ[base + 3] = csq.w;
    __syncthreads();
    if (tid < 128) {
        float s = 0.f, q = 0.f;
        #pragma unroll
        for (int t = 0; t < 8; t++) {
            s += redS[t * 128 + tid];
            q += redQ[t * 128 + tid];
        }
        atomicAdd(&g_sum[tid], s);
        atomicAdd(&g_sumsq[tid], q);
    }
}

// ---------------- plain GEMM for layer 3: y = relu(bn2(h2)) @ W3, scaled by n_out ----------------
__global__ __launch_bounds__(256)
void gemm64_kernel(const float* __restrict__ A,
                   const float* __restrict__ W,
                   float* __restrict__ out) {
    constexpr int COLV = 16;   // 64 cols = 16 float4
    constexpr int TYC  = 16;
    constexpr int RPT  = 4;

    extern __shared__ float4 smem4[];
    float4* As = smem4;               // 64 x 32 float4
    float4* Ws = As + 64 * 32;        // 128 x 16 float4

    int tid = threadIdx.x;
    int rowBase = blockIdx.x * 64;

    for (int i = tid; i < 128 * COLV; i += 256)
        Ws[i] = ((const float4*)W)[i];

    #pragma unroll
    for (int i = 0; i < 8; i++) {
        int slot = tid + i * 256;
        int lrow = slot >> 5;
        int kk = slot & 31;
        int grow = rowBase + lrow;
        float4 v = make_float4(0.f, 0.f, 0.f, 0.f);
        if (grow < N_NODES) {
            v = ((const float4*)A)[(size_t)grow * 32 + kk];
            float4 a4 = ((const float4*)g_bna)[kk];
            float4 b4 = ((const float4*)g_bnb)[kk];
            v.x = fmaxf(fmaf(v.x, a4.x, b4.x), 0.f);
            v.y = fmaxf(fmaf(v.y, a4.y, b4.y), 0.f);
            v.z = fmaxf(fmaf(v.z, a4.z, b4.z), 0.f);
            v.w = fmaxf(fmaf(v.w, a4.w, b4.w), 0.f);
        }
        As[slot] = v;
    }
    __syncthreads();

    int tx = tid % COLV;
    int ty = tid / COLV;

    float4 acc[RPT];
    #pragma unroll
    for (int r = 0; r < RPT; r++) acc[r] = make_float4(0.f, 0.f, 0.f, 0.f);

    #pragma unroll 8
    for (int k4 = 0; k4 < 32; k4++) {
        float4 w0 = Ws[(k4 * 4 + 0) * COLV + tx];
        float4 w1 = Ws[(k4 * 4 + 1) * COLV + tx];
        float4 w2 = Ws[(k4 * 4 + 2) * COLV + tx];
        float4 w3 = Ws[(k4 * 4 + 3) * COLV + tx];
        #pragma unroll
        for (int r = 0; r < RPT; r++) {
            float4 av = As[(ty + r * TYC) * 32 + k4];
            acc[r].x += av.x * w0.x + av.y * w1.x + av.z * w2.x + av.w * w3.x;
            acc[r].y += av.x * w0.y + av.y * w1.y + av.z * w2.y + av.w * w3.y;
            acc[r].z += av.x * w0.z + av.y * w1.z + av.z * w2.z + av.w * w3.z;
            acc[r].w += av.x * w0.w + av.y * w1.w + av.z * w2.w + av.w * w3.w;
        }
    }

    #pragma unroll
    for (int r = 0; r < RPT; r++) {
        int grow = rowBase + ty + r * TYC;
        if (grow < N_NODES) {
            float s = g_nout[grow];
            float4 h = acc[r];
            h.x *= s; h.y *= s; h.z *= s; h.w *= s;
            ((float4*)out)[(size_t)grow * COLV + tx] = h;
        }
    }
}

// ---------------- BN finalize: derive (a,b), reset accumulators ----------------
__global__ void bn_finalize_kernel(const float* __restrict__ gamma,
                                   const float* __restrict__ beta) {
    int t = threadIdx.x;
    if (t < F_HID) {
        float mean = g_sum[t] / (float)N_NODES;
        float var = g_sumsq[t] / (float)N_NODES - mean * mean;
        float a = gamma[t] * rsqrtf(var + BN_EPS);
        g_bna[t] = a;
        g_bnb[t] = fmaf(-mean, a, beta[t]);
        g_sum[t] = 0.f;
        g_sumsq[t] = 0.f;
    }
}

// ---------------- final CSR gather (64 feats): out = n_in * sum(y[src]) + b3 ----------------
__global__ void gather64_kernel(const float* __restrict__ y,
                                const float* __restrict__ b3,
                                float* __restrict__ out) {
    int w = (blockIdx.x * blockDim.x + threadIdx.x) >> 5;   // dst node
    int lane = threadIdx.x & 31;                            // owns float2
    if (w >= N_NODES) return;
    const float2* y2 = (const float2*)y;
    int beg = g_row_ptr[w];
    int end = g_row_ptr[w + 1];
    float2 acc = make_float2(0.f, 0.f);
    int j = beg;
    for (; j + 4 <= end; j += 4) {
        int s0 = g_csr_src[j + 0];
        int s1 = g_csr_src[j + 1];
        int s2 = g_csr_src[j + 2];
        int s3 = g_csr_src[j + 3];
        float2 v0 = y2[(size_t)s0 * 32 + lane];
        float2 v1 = y2[(size_t)s1 * 32 + lane];
        float2 v2 = y2[(size_t)s2 * 32 + lane];
        float2 v3 = y2[(size_t)s3 * 32 + lane];
        acc.x += (v0.x + v1.x) + (v2.x + v3.x);
        acc.y += (v0.y + v1.y) + (v2.y + v3.y);
    }
    for (; j < end; j++) {
        int s = g_csr_src[j];
        float2 v = y2[(size_t)s * 32 + lane];
        acc.x += v.x; acc.y += v.y;
    }
    float ni = g_nin[w];
    float2 b = ((const float2*)b3)[lane];
    float2 o;
    o.x = fmaf(acc.x, ni, b.x);
    o.y = fmaf(acc.y, ni, b.y);
    ((float2*)out)[(size_t)w * 32 + lane] = o;
}

// ---------------- host launcher ----------------
extern "C" void kernel_launch(void* const* d_in, const int* in_sizes, int n_in,
                              void* d_out, int out_size) {
    const float* features = (const float*)d_in[0];
    const int*   srcbuf   = (const int*)d_in[1];   // int32 or int64 (detected on device)
    const int*   dstbuf   = (const int*)d_in[2];
    const float* W1  = (const float*)d_in[3];
    const float* b1  = (const float*)d_in[4];
    const float* ga1 = (const float*)d_in[5];
    const float* be1 = (const float*)d_in[6];
    const float* W2  = (const float*)d_in[7];
    const float* b2  = (const float*)d_in[8];
    const float* ga2 = (const float*)d_in[9];
    const float* be2 = (const float*)d_in[10];
    const float* W3  = (const float*)d_in[11];
    const float* b3  = (const float*)d_in[12];
    float* out = (float*)d_out;

    void* p;
    cudaGetSymbolAddress(&p, g_agg);
    float* p_agg = (float*)p;
    cudaGetSymbolAddress(&p, g_h);
    float* p_h = (float*)p;

    constexpr int SM128 = 64 * 32 * 16 + 128 * 32 * 16 + 2 * 8 * 128 * 4;   // 106496
    constexpr int SM64  = 64 * 32 * 16 + 128 * 16 * 16;                     // 65536

    cudaFuncSetAttribute(fused_conv_kernel<1>,
                         cudaFuncAttributeMaxDynamicSharedMemorySize, SM128);
    cudaFuncSetAttribute(fused_conv_kernel<2>,
                         cudaFuncAttributeMaxDynamicSharedMemorySize, SM128);
    cudaFuncSetAttribute(gemm64_kernel,
                         cudaFuncAttributeMaxDynamicSharedMemorySize, SM64);

    int nblk = (N_NODES + 255) / 256;
    int eblk = (N_EDGES + 255) / 256;
    int gblk = (N_NODES + 63) / 64;

    // graph preprocessing: init+detect, degrees, scan(2 passes, norms fused), CSR fill
    init_detect_kernel<<<nblk, 256>>>(srcbuf);          // launch 0
    convert_degree_kernel<<<eblk, 256>>>(srcbuf, dstbuf); // 1
    scanA_kernel<<<SCAN_BLOCKS, 1024>>>();              // 2
    scanB_kernel<<<SCAN_BLOCKS, 1024>>>();              // 3
    fill_csr_kernel<<<eblk, 256>>>();                   // 4

    // ---- layer 1 ---- (launch 5: profiled by ncu -s 5)
    fused_conv_kernel<1><<<gblk, 256, SM128>>>(features, W1, b1, p_h);
    bn_finalize_kernel<<<1, 128>>>(ga1, be1);

    // ---- layer 2 ----
    fused_conv_kernel<2><<<gblk, 256, SM128>>>(p_h, W2, b2, p_agg);
    bn_finalize_kernel<<<1, 128>>>(ga2, be2);

    // ---- layer 3: GEMM first (aggregation commutes with W3), then CSR gather ----
    gemm64_kernel<<<gblk, 256, SM64>>>(p_agg, W3, p_h);   // y = relu(bn2(h2))@W3 * n_out
    gather64_kernel<<<(N_NODES + 7) / 8, 256>>>(p_h, b3, out);
}

// round 6
// speedup vs baseline: 2.5039x; 1.1172x over previous
#include <cuda_runtime.h>
#include <cstdint>

#define N_NODES 100000
#define N_EDGES 1600000
#define F_HID 128
#define F_OUT 64
#define BN_EPS 1e-5f
#define SCAN_BLOCKS 98            // 98 * 1024 = 100352 >= N_NODES

// ---------------- device-global scratch (no allocations allowed) ----------------
__device__ __align__(16) float g_nout[N_NODES];                 // rsqrt(max(deg_out,1))
__device__ __align__(16) float g_nin[N_NODES];                  // rsqrt(max(deg_in,1))
__device__ __align__(16) float g_h1[(size_t)N_NODES * F_HID];   // layer buffers
__device__ __align__(16) float g_h2[(size_t)N_NODES * F_HID];
__device__ __align__(16) int   g_csr_src[N_EDGES];              // src ids bucketed by dst
__device__ __align__(16) int   g_row_ptr[N_NODES + 1];
__device__ __align__(16) int   g_cursor[N_NODES];
__device__ __align__(16) int   g_deg_out[N_NODES];
__device__ __align__(16) int   g_deg_in[N_NODES];
__device__ __align__(16) int   g_partial[128];                  // scan block partials
__device__ __align__(16) float g_sum[F_HID];
__device__ __align__(16) float g_sumsq[F_HID];
__device__ __align__(16) float g_bna[F_HID];                    // BN scale a = g*rsqrt(var+eps)
__device__ __align__(16) float g_bnb[F_HID];                    // BN shift b = be - mean*a
__device__ int g_idx_is64;                                      // dtype flag

// ---------------- tf32 helpers ----------------
__device__ __forceinline__ uint32_t f2tf(float v) {
    uint32_t r;
    asm("cvt.rna.tf32.f32 %0, %1;" : "=r"(r) : "f"(v));
    return r;
}

__device__ __forceinline__ void mma_tf32(float* c, const uint32_t* a,
                                         uint32_t b0, uint32_t b1) {
    asm volatile(
        "mma.sync.aligned.m16n8k8.row.col.f32.tf32.tf32.f32 "
        "{%0,%1,%2,%3}, {%4,%5,%6,%7}, {%8,%9}, {%0,%1,%2,%3};"
        : "+f"(c[0]), "+f"(c[1]), "+f"(c[2]), "+f"(c[3])
        : "r"(a[0]), "r"(a[1]), "r"(a[2]), "r"(a[3]), "r"(b0), "r"(b1));
}

__device__ __forceinline__ float4 bn_relu4(float4 v, float4 a, float4 c) {
    v.x = fmaxf(fmaf(v.x, a.x, c.x), 0.f);
    v.y = fmaxf(fmaf(v.y, a.y, c.y), 0.f);
    v.z = fmaxf(fmaf(v.z, a.z, c.z), 0.f);
    v.w = fmaxf(fmaf(v.w, a.w, c.w), 0.f);
    return v;
}

// ---------------- init + dtype detection ----------------
// If indices are int64 (values < 1e5 << 2^31), every odd 32-bit word is 0.
__global__ void init_detect_kernel(const int* __restrict__ srcbuf) {
    int i = blockIdx.x * blockDim.x + threadIdx.x;
    if (i < N_NODES) { g_deg_out[i] = 0; g_deg_in[i] = 0; }
    if (i < F_HID) { g_sum[i] = 0.f; g_sumsq[i] = 0.f; }
    if (blockIdx.x == 0 && threadIdx.x == 0) {
        int all_zero = 1;
        #pragma unroll 1
        for (int k = 0; k < 64; k++) {
            if (srcbuf[2 * k + 1] != 0) { all_zero = 0; break; }
        }
        g_idx_is64 = all_zero;
    }
}

// ---------------- degree histogram (reads raw buffers) ----------------
__global__ void degree_kernel(const int* __restrict__ sbuf,
                              const int* __restrict__ dbuf) {
    int e = blockIdx.x * blockDim.x + threadIdx.x;
    if (e < N_EDGES) {
        int is64 = g_idx_is64;
        int s = is64 ? sbuf[2 * e] : sbuf[e];
        int d = is64 ? dbuf[2 * e] : dbuf[e];
        atomicAdd(&g_deg_out[s], 1);
        atomicAdd(&g_deg_in[d], 1);
    }
}

// ---------------- scan pass A: per-block sums of deg_in ----------------
__global__ __launch_bounds__(1024) void scanA_kernel() {
    __shared__ int wsum[32];
    int tid = threadIdx.x, lane = tid & 31, wid = tid >> 5;
    int i = blockIdx.x * 1024 + tid;
    int v = (i < N_NODES) ? g_deg_in[i] : 0;
    int s = v;
    #pragma unroll
    for (int off = 16; off > 0; off >>= 1)
        s += __shfl_down_sync(0xffffffffu, s, off);
    if (lane == 0) wsum[wid] = s;
    __syncthreads();
    if (wid == 0) {
        int t = wsum[lane];
        #pragma unroll
        for (int off = 16; off > 0; off >>= 1)
            t += __shfl_down_sync(0xffffffffu, t, off);
        if (lane == 0) g_partial[blockIdx.x] = t;
    }
}

// ---------------- scan pass B: offsets + local scan + norms ----------------
__global__ __launch_bounds__(1024) void scanB_kernel() {
    __shared__ int wsum[32];
    __shared__ int blockOffset;
    int tid = threadIdx.x, lane = tid & 31, wid = tid >> 5;

    if (wid == 0) {
        int acc = 0;
        for (int j = lane; j < blockIdx.x; j += 32) acc += g_partial[j];
        #pragma unroll
        for (int off = 16; off > 0; off >>= 1)
            acc += __shfl_down_sync(0xffffffffu, acc, off);
        if (lane == 0) blockOffset = acc;
    }

    int i = blockIdx.x * 1024 + tid;
    int v = (i < N_NODES) ? g_deg_in[i] : 0;
    int incl = v;
    #pragma unroll
    for (int off = 1; off < 32; off <<= 1) {
        int t = __shfl_up_sync(0xffffffffu, incl, off);
        if (lane >= off) incl += t;
    }
    if (lane == 31) wsum[wid] = incl;
    __syncthreads();
    if (wid == 0) {
        int wv = wsum[lane];
        int winc = wv;
        #pragma unroll
        for (int off = 1; off < 32; off <<= 1) {
            int t = __shfl_up_sync(0xffffffffu, winc, off);
            if (lane >= off) winc += t;
        }
        wsum[lane] = winc - wv;
    }
    __syncthreads();
    int excl = blockOffset + wsum[wid] + incl - v;
    if (i < N_NODES) {
        g_row_ptr[i] = excl;
        g_cursor[i] = excl;
        g_nout[i] = rsqrtf(fmaxf((float)g_deg_out[i], 1.f));
        g_nin[i]  = rsqrtf(fmaxf((float)v, 1.f));
        if (i == N_NODES - 1) g_row_ptr[N_NODES] = excl + v;
    }
}

// ---------------- bucket fill ----------------
__global__ void fill_csr_kernel(const int* __restrict__ sbuf,
                                const int* __restrict__ dbuf) {
    int e = blockIdx.x * blockDim.x + threadIdx.x;
    if (e < N_EDGES) {
        int is64 = g_idx_is64;
        int s = is64 ? sbuf[2 * e] : sbuf[e];
        int d = is64 ? dbuf[2 * e] : dbuf[e];
        int pos = atomicAdd(&g_cursor[d], 1);
        g_csr_src[pos] = s;
    }
}

// ---------------- fused CSR-gather + 3xTF32 mma GEMM (128 -> 128) ----------------
// smem: As 64 rows x stride 132 fl; Wt transposed [n][k] stride 133 fl; red 2x4x128.
template<int LAYER>
__global__ __launch_bounds__(256)
void fused_conv_kernel(const float* __restrict__ x,
                       const float* __restrict__ W,
                       const float* __restrict__ bias,
                       float* __restrict__ out) {
    extern __shared__ float smem[];
    float*  As_f = smem;                    // 64*132
    float4* As4  = (float4*)smem;           // rows stride 33 float4
    float*  Wt   = smem + 64 * 132;         // 128*133 (transposed W)
    float*  redS = Wt + 128 * 133;          // 4*128
    float*  redQ = redS + 512;              // 4*128

    int tid = threadIdx.x;
    int lane = tid & 31;
    int wid = tid >> 5;
    int rowBase = blockIdx.x * 64;
    const float4* x4 = (const float4*)x;

    // stage W transposed: Wt[n*133 + k] = W[k*128 + n]; coalesced reads, conflict-free writes
    for (int i = tid; i < 128 * 128; i += 256) {
        int k = i >> 7, n = i & 127;
        Wt[n * 133 + k] = W[i];
    }

    float4 a4 = make_float4(0.f, 0.f, 0.f, 0.f);
    float4 c4 = make_float4(0.f, 0.f, 0.f, 0.f);
    if (LAYER == 2) {
        a4 = ((const float4*)g_bna)[lane];
        c4 = ((const float4*)g_bnb)[lane];
    }

    // gather phase: one warp per row, unroll-8 for MLP
    for (int r = wid; r < 64; r += 8) {
        int grow = rowBase + r;
        float4 acc = make_float4(0.f, 0.f, 0.f, 0.f);
        if (grow < N_NODES) {
            int beg = g_row_ptr[grow];
            int end = g_row_ptr[grow + 1];
            int j = beg;
            for (; j + 8 <= end; j += 8) {
                int ss[8]; float nn[8]; float4 vv[8];
                #pragma unroll
                for (int u = 0; u < 8; u++) ss[u] = g_csr_src[j + u];
                #pragma unroll
                for (int u = 0; u < 8; u++) nn[u] = g_nout[ss[u]];
                #pragma unroll
                for (int u = 0; u < 8; u++) vv[u] = x4[(size_t)ss[u] * 32 + lane];
                #pragma unroll
                for (int u = 0; u < 8; u++) {
                    float4 v = (LAYER == 2) ? bn_relu4(vv[u], a4, c4) : vv[u];
                    acc.x = fmaf(v.x, nn[u], acc.x);
                    acc.y = fmaf(v.y, nn[u], acc.y);
                    acc.z = fmaf(v.z, nn[u], acc.z);
                    acc.w = fmaf(v.w, nn[u], acc.w);
                }
            }
            for (; j < end; j++) {
                int s = g_csr_src[j];
                float n = g_nout[s];
                float4 v = x4[(size_t)s * 32 + lane];
                if (LAYER == 2) v = bn_relu4(v, a4, c4);
                acc.x = fmaf(v.x, n, acc.x);
                acc.y = fmaf(v.y, n, acc.y);
                acc.z = fmaf(v.z, n, acc.z);
                acc.w = fmaf(v.w, n, acc.w);
            }
            float ni = g_nin[grow];
            acc.x *= ni; acc.y *= ni; acc.z *= ni; acc.w *= ni;
        }
        As4[r * 33 + lane] = acc;
    }
    __syncthreads();

    // mma phase: warp (warp_m 0..3, wn 0..1) computes m16 x n64, K=128
    int warp_m = wid & 3;
    int wn = wid >> 2;
    int qr = lane >> 2;       // 0..7
    int rr = lane & 3;        // 0..3
    int m0 = warp_m * 16 + qr;

    float c[8][4];
    #pragma unroll
    for (int nt = 0; nt < 8; nt++)
        #pragma unroll
        for (int q = 0; q < 4; q++) c[nt][q] = 0.f;

    #pragma unroll 2
    for (int ks = 0; ks < 16; ks++) {
        int k0 = ks * 8;
        float av0 = As_f[m0 * 132 + k0 + rr];
        float av1 = As_f[(m0 + 8) * 132 + k0 + rr];
        float av2 = As_f[m0 * 132 + k0 + 4 + rr];
        float av3 = As_f[(m0 + 8) * 132 + k0 + 4 + rr];
        uint32_t ah[4], al[4];
        ah[0] = f2tf(av0); al[0] = f2tf(av0 - __uint_as_float(ah[0]));
        ah[1] = f2tf(av1); al[1] = f2tf(av1 - __uint_as_float(ah[1]));
        ah[2] = f2tf(av2); al[2] = f2tf(av2 - __uint_as_float(ah[2]));
        ah[3] = f2tf(av3); al[3] = f2tf(av3 - __uint_as_float(ah[3]));
        #pragma unroll
        for (int nt = 0; nt < 8; nt++) {
            int nb = (wn * 64 + nt * 8 + qr) * 133 + k0 + rr;
            float b0 = Wt[nb];
            float b1 = Wt[nb + 4];
            uint32_t bh0 = f2tf(b0);
            uint32_t bh1 = f2tf(b1);
            uint32_t bl0 = __float_as_uint(b0 - __uint_as_float(bh0));
            uint32_t bl1 = __float_as_uint(b1 - __uint_as_float(bh1));
            mma_tf32(c[nt], ah, bh0, bh1);   // hi*hi
            mma_tf32(c[nt], al, bh0, bh1);   // lo*hi
            mma_tf32(c[nt], ah, bl0, bl1);   // hi*lo
        }
    }

    // epilogue: bias, store, BN stats
    int g0 = rowBase + m0;
    int g1 = g0 + 8;
    bool v0r = (g0 < N_NODES), v1r = (g1 < N_NODES);
    #pragma unroll
    for (int nt = 0; nt < 8; nt++) {
        int col = wn * 64 + nt * 8 + 2 * rr;
        float b0 = bias[col], b1 = bias[col + 1];
        float h00 = c[nt][0] + b0, h01 = c[nt][1] + b1;
        float h10 = c[nt][2] + b0, h11 = c[nt][3] + b1;
        if (v0r) *(float2*)&out[(size_t)g0 * 128 + col] = make_float2(h00, h01);
        if (v1r) *(float2*)&out[(size_t)g1 * 128 + col] = make_float2(h10, h11);
        float sA = (v0r ? h00 : 0.f) + (v1r ? h10 : 0.f);
        float sB = (v0r ? h01 : 0.f) + (v1r ? h11 : 0.f);
        float qA = (v0r ? h00 * h00 : 0.f) + (v1r ? h10 * h10 : 0.f);
        float qB = (v0r ? h01 * h01 : 0.f) + (v1r ? h11 * h11 : 0.f);
        #pragma unroll
        for (int off = 16; off >= 4; off >>= 1) {
            sA += __shfl_down_sync(0xffffffffu, sA, off);
            sB += __shfl_down_sync(0xffffffffu, sB, off);
            qA += __shfl_down_sync(0xffffffffu, qA, off);
            qB += __shfl_down_sync(0xffffffffu, qB, off);
        }
        if (lane < 4) {
            *(float2*)&redS[warp_m * 128 + col] = make_float2(sA, sB);
            *(float2*)&redQ[warp_m * 128 + col] = make_float2(qA, qB);
        }
    }
    __syncthreads();
    if (tid < 128) {
        float s = redS[tid] + redS[128 + tid] + redS[256 + tid] + redS[384 + tid];
        float q = redQ[tid] + redQ[128 + tid] + redQ[256 + tid] + redQ[384 + tid];
        atomicAdd(&g_sum[tid], s);
        atomicAdd(&g_sumsq[tid], q);
    }
}

// ---------------- layer-3 mma GEMM: y = relu(bn2(h2)) @ W3 * n_out ----------------
__global__ __launch_bounds__(256)
void mma_gemm64_kernel(const float* __restrict__ A,
                       const float* __restrict__ W,
                       float* __restrict__ out) {
    extern __shared__ float smem[];
    float*  As_f = smem;                    // 64*132
    float4* As4  = (float4*)smem;
    float*  Wt   = smem + 64 * 132;         // 64*133 (transposed W3)

    int tid = threadIdx.x;
    int rowBase = blockIdx.x * 64;

    // stage W3 transposed: Wt[n*133 + k] = W[k*64 + n]
    for (int i = tid; i < 128 * 64; i += 256) {
        int k = i >> 6, n = i & 63;
        Wt[n * 133 + k] = W[i];
    }

    // stage A with BN+ReLU
    #pragma unroll
    for (int i = 0; i < 8; i++) {
        int slot = tid + i * 256;
        int lrow = slot >> 5;
        int kk = slot & 31;
        int grow = rowBase + lrow;
        float4 v = make_float4(0.f, 0.f, 0.f, 0.f);
        if (grow < N_NODES) {
            v = ((const float4*)A)[(size_t)grow * 32 + kk];
            float4 a4 = ((const float4*)g_bna)[kk];
            float4 b4 = ((const float4*)g_bnb)[kk];
            v = bn_relu4(v, a4, b4);
        }
        As4[lrow * 33 + kk] = v;
    }
    __syncthreads();

    int lane = tid & 31;
    int wid = tid >> 5;
    int warp_m = wid & 3;
    int wn = wid >> 2;
    int qr = lane >> 2;
    int rr = lane & 3;
    int m0 = warp_m * 16 + qr;

    float c[4][4];
    #pragma unroll
    for (int nt = 0; nt < 4; nt++)
        #pragma unroll
        for (int q = 0; q < 4; q++) c[nt][q] = 0.f;

    #pragma unroll 2
    for (int ks = 0; ks < 16; ks++) {
        int k0 = ks * 8;
        float av0 = As_f[m0 * 132 + k0 + rr];
        float av1 = As_f[(m0 + 8) * 132 + k0 + rr];
        float av2 = As_f[m0 * 132 + k0 + 4 + rr];
        float av3 = As_f[(m0 + 8) * 132 + k0 + 4 + rr];
        uint32_t ah[4], al[4];
        ah[0] = f2tf(av0); al[0] = f2tf(av0 - __uint_as_float(ah[0]));
        ah[1] = f2tf(av1); al[1] = f2tf(av1 - __uint_as_float(ah[1]));
        ah[2] = f2tf(av2); al[2] = f2tf(av2 - __uint_as_float(ah[2]));
        ah[3] = f2tf(av3); al[3] = f2tf(av3 - __uint_as_float(ah[3]));
        #pragma unroll
        for (int nt = 0; nt < 4; nt++) {
            int nb = (wn * 32 + nt * 8 + qr) * 133 + k0 + rr;
            float b0 = Wt[nb];
            float b1 = Wt[nb + 4];
            uint32_t bh0 = f2tf(b0);
            uint32_t bh1 = f2tf(b1);
            uint32_t bl0 = __float_as_uint(b0 - __uint_as_float(bh0));
            uint32_t bl1 = __float_as_uint(b1 - __uint_as_float(bh1));
            mma_tf32(c[nt], ah, bh0, bh1);
            mma_tf32(c[nt], al, bh0, bh1);
            mma_tf32(c[nt], ah, bl0, bl1);
        }
    }

    int g0 = rowBase + m0;
    int g1 = g0 + 8;
    float s0 = (g0 < N_NODES) ? g_nout[g0] : 0.f;
    float s1 = (g1 < N_NODES) ? g_nout[g1] : 0.f;
    #pragma unroll
    for (int nt = 0; nt < 4; nt++) {
        int col = wn * 32 + nt * 8 + 2 * rr;
        if (g0 < N_NODES)
            *(float2*)&out[(size_t)g0 * 64 + col] =
                make_float2(c[nt][0] * s0, c[nt][1] * s0);
        if (g1 < N_NODES)
            *(float2*)&out[(size_t)g1 * 64 + col] =
                make_float2(c[nt][2] * s1, c[nt][3] * s1);
    }
}

// ---------------- BN finalize ----------------
__global__ void bn_finalize_kernel(const float* __restrict__ gamma,
                                   const float* __restrict__ beta) {
    int t = threadIdx.x;
    if (t < F_HID) {
        float mean = g_sum[t] / (float)N_NODES;
        float var = g_sumsq[t] / (float)N_NODES - mean * mean;
        float a = gamma[t] * rsqrtf(var + BN_EPS);
        g_bna[t] = a;
        g_bnb[t] = fmaf(-mean, a, beta[t]);
        g_sum[t] = 0.f;
        g_sumsq[t] = 0.f;
    }
}

// ---------------- final CSR gather (64 feats): out = n_in * sum(y[src]) + b3 ----------------
__global__ void gather64_kernel(const float* __restrict__ y,
                                const float* __restrict__ b3,
                                float* __restrict__ out) {
    int w = (blockIdx.x * blockDim.x + threadIdx.x) >> 5;   // dst node
    int lane = threadIdx.x & 31;                            // owns float2
    if (w >= N_NODES) return;
    const float2* y2 = (const float2*)y;
    int beg = g_row_ptr[w];
    int end = g_row_ptr[w + 1];
    float2 acc = make_float2(0.f, 0.f);
    int j = beg;
    for (; j + 8 <= end; j += 8) {
        int ss[8]; float2 vv[8];
        #pragma unroll
        for (int u = 0; u < 8; u++) ss[u] = g_csr_src[j + u];
        #pragma unroll
        for (int u = 0; u < 8; u++) vv[u] = y2[(size_t)ss[u] * 32 + lane];
        #pragma unroll
        for (int u = 0; u < 8; u++) { acc.x += vv[u].x; acc.y += vv[u].y; }
    }
    for (; j < end; j++) {
        int s = g_csr_src[j];
        float2 v = y2[(size_t)s * 32 + lane];
        acc.x += v.x; acc.y += v.y;
    }
    float ni = g_nin[w];
    float2 b = ((const float2*)b3)[lane];
    float2 o;
    o.x = fmaf(acc.x, ni, b.x);
    o.y = fmaf(acc.y, ni, b.y);
    ((float2*)out)[(size_t)w * 32 + lane] = o;
}

// ---------------- host launcher ----------------
extern "C" void kernel_launch(void* const* d_in, const int* in_sizes, int n_in,
                              void* d_out, int out_size) {
    const float* features = (const float*)d_in[0];
    const int*   srcbuf   = (const int*)d_in[1];   // int32 or int64 (detected on device)
    const int*   dstbuf   = (const int*)d_in[2];
    const float* W1  = (const float*)d_in[3];
    const float* b1  = (const float*)d_in[4];
    const float* ga1 = (const float*)d_in[5];
    const float* be1 = (const float*)d_in[6];
    const float* W2  = (const float*)d_in[7];
    const float* b2  = (const float*)d_in[8];
    const float* ga2 = (const float*)d_in[9];
    const float* be2 = (const float*)d_in[10];
    const float* W3  = (const float*)d_in[11];
    const float* b3  = (const float*)d_in[12];
    float* out = (float*)d_out;

    void* p;
    cudaGetSymbolAddress(&p, g_h1);
    float* p_h1 = (float*)p;
    cudaGetSymbolAddress(&p, g_h2);
    float* p_h2 = (float*)p;

    constexpr int SM_CONV = (64 * 132 + 128 * 133 + 1024) * 4;   // 105984
    constexpr int SM_G64  = (64 * 132 + 64 * 133) * 4;           // 67840

    cudaFuncSetAttribute(fused_conv_kernel<1>,
                         cudaFuncAttributeMaxDynamicSharedMemorySize, SM_CONV);
    cudaFuncSetAttribute(fused_conv_kernel<2>,
                         cudaFuncAttributeMaxDynamicSharedMemorySize, SM_CONV);
    cudaFuncSetAttribute(mma_gemm64_kernel,
                         cudaFuncAttributeMaxDynamicSharedMemorySize, SM_G64);

    int nblk = (N_NODES + 255) / 256;
    int eblk = (N_EDGES + 255) / 256;
    int gblk = (N_NODES + 63) / 64;

    // graph preprocessing
    init_detect_kernel<<<nblk, 256>>>(srcbuf);
    degree_kernel<<<eblk, 256>>>(srcbuf, dstbuf);
    scanA_kernel<<<SCAN_BLOCKS, 1024>>>();
    scanB_kernel<<<SCAN_BLOCKS, 1024>>>();
    fill_csr_kernel<<<eblk, 256>>>(srcbuf, dstbuf);

    // ---- layer 1 ----
    fused_conv_kernel<1><<<gblk, 256, SM_CONV>>>(features, W1, b1, p_h1);
    bn_finalize_kernel<<<1, 128>>>(ga1, be1);

    // ---- layer 2 ----
    fused_conv_kernel<2><<<gblk, 256, SM_CONV>>>(p_h1, W2, b2, p_h2);
    bn_finalize_kernel<<<1, 128>>>(ga2, be2);

    // ---- layer 3: GEMM first (aggregation commutes with W3), then CSR gather ----
    mma_gemm64_kernel<<<gblk, 256, SM_G64>>>(p_h2, W3, p_h1);
    gather64_kernel<<<(N_NODES + 7) / 8, 256>>>(p_h1, b3, out);
}

// round 7
// speedup vs baseline: 2.5538x; 1.0200x over previous
#include <cuda_runtime.h>
#include <cstdint>

#define N_NODES 100000
#define N_EDGES 1600000
#define F_HID 128
#define F_OUT 64
#define BN_EPS 1e-5f
#define SCAN_BLOCKS 98            // 98 * 1024 = 100352 >= N_NODES

// ---------------- device-global scratch (no allocations allowed) ----------------
__device__ __align__(16) float g_nout[N_NODES];                 // rsqrt(max(deg_out,1))
__device__ __align__(16) float g_nin[N_NODES];                  // rsqrt(max(deg_in,1))
__device__ __align__(16) float g_h1[(size_t)N_NODES * F_HID];   // layer buffers
__device__ __align__(16) float g_h2[(size_t)N_NODES * F_HID];
__device__ __align__(16) int2  g_csr_pack[N_EDGES];             // {src, nout_bits} by dst
__device__ __align__(16) int   g_row_ptr[N_NODES + 1];
__device__ __align__(16) int   g_cursor[N_NODES];
__device__ __align__(16) int   g_deg_out[N_NODES];
__device__ __align__(16) int   g_deg_in[N_NODES];
__device__ __align__(16) int   g_partial[128];                  // scan block partials
__device__ __align__(16) float g_sum[F_HID];
__device__ __align__(16) float g_sumsq[F_HID];
__device__ __align__(16) float g_bna[F_HID];                    // BN scale a = g*rsqrt(var+eps)
__device__ __align__(16) float g_bnb[F_HID];                    // BN shift b = be - mean*a
__device__ int g_idx_is64;                                      // dtype flag

// ---------------- tf32 helpers ----------------
__device__ __forceinline__ uint32_t f2tf(float v) {
    uint32_t r;
    asm("cvt.rna.tf32.f32 %0, %1;" : "=r"(r) : "f"(v));
    return r;
}

__device__ __forceinline__ void mma_tf32(float* c, const uint32_t* a,
                                         uint32_t b0, uint32_t b1) {
    asm volatile(
        "mma.sync.aligned.m16n8k8.row.col.f32.tf32.tf32.f32 "
        "{%0,%1,%2,%3}, {%4,%5,%6,%7}, {%8,%9}, {%0,%1,%2,%3};"
        : "+f"(c[0]), "+f"(c[1]), "+f"(c[2]), "+f"(c[3])
        : "r"(a[0]), "r"(a[1]), "r"(a[2]), "r"(a[3]), "r"(b0), "r"(b1));
}

__device__ __forceinline__ float4 bn_relu4(float4 v, float4 a, float4 c) {
    v.x = fmaxf(fmaf(v.x, a.x, c.x), 0.f);
    v.y = fmaxf(fmaf(v.y, a.y, c.y), 0.f);
    v.z = fmaxf(fmaf(v.z, a.z, c.z), 0.f);
    v.w = fmaxf(fmaf(v.w, a.w, c.w), 0.f);
    return v;
}

// ---------------- dtype detection ----------------
// If indices are int64 (values < 1e5 << 2^31), every odd 32-bit word is 0.
__global__ void detect_kernel(const int* __restrict__ srcbuf) {
    if (threadIdx.x == 0) {
        int all_zero = 1;
        #pragma unroll 1
        for (int k = 0; k < 64; k++) {
            if (srcbuf[2 * k + 1] != 0) { all_zero = 0; break; }
        }
        g_idx_is64 = all_zero;
    }
}

// ---------------- degree histogram ----------------
__global__ void degree_kernel(const int* __restrict__ sbuf,
                              const int* __restrict__ dbuf) {
    int e = blockIdx.x * blockDim.x + threadIdx.x;
    if (e < N_EDGES) {
        int is64 = g_idx_is64;
        int s = is64 ? ((const int2*)sbuf)[e].x : sbuf[e];
        int d = is64 ? ((const int2*)dbuf)[e].x : dbuf[e];
        atomicAdd(&g_deg_out[s], 1);
        atomicAdd(&g_deg_in[d], 1);
    }
}

// ---------------- scan pass A: per-block sums of deg_in ----------------
__global__ __launch_bounds__(1024) void scanA_kernel() {
    __shared__ int wsum[32];
    int tid = threadIdx.x, lane = tid & 31, wid = tid >> 5;
    int i = blockIdx.x * 1024 + tid;
    int v = (i < N_NODES) ? g_deg_in[i] : 0;
    int s = v;
    #pragma unroll
    for (int off = 16; off > 0; off >>= 1)
        s += __shfl_down_sync(0xffffffffu, s, off);
    if (lane == 0) wsum[wid] = s;
    __syncthreads();
    if (wid == 0) {
        int t = wsum[lane];
        #pragma unroll
        for (int off = 16; off > 0; off >>= 1)
            t += __shfl_down_sync(0xffffffffu, t, off);
        if (lane == 0) g_partial[blockIdx.x] = t;
    }
}

// ---------------- scan pass B: offsets + local scan + norms ----------------
__global__ __launch_bounds__(1024) void scanB_kernel() {
    __shared__ int wsum[32];
    __shared__ int blockOffset;
    int tid = threadIdx.x, lane = tid & 31, wid = tid >> 5;

    if (wid == 0) {
        int acc = 0;
        for (int j = lane; j < blockIdx.x; j += 32) acc += g_partial[j];
        #pragma unroll
        for (int off = 16; off > 0; off >>= 1)
            acc += __shfl_down_sync(0xffffffffu, acc, off);
        if (lane == 0) blockOffset = acc;
    }

    int i = blockIdx.x * 1024 + tid;
    int v = (i < N_NODES) ? g_deg_in[i] : 0;
    int incl = v;
    #pragma unroll
    for (int off = 1; off < 32; off <<= 1) {
        int t = __shfl_up_sync(0xffffffffu, incl, off);
        if (lane >= off) incl += t;
    }
    if (lane == 31) wsum[wid] = incl;
    __syncthreads();
    if (wid == 0) {
        int wv = wsum[lane];
        int winc = wv;
        #pragma unroll
        for (int off = 1; off < 32; off <<= 1) {
            int t = __shfl_up_sync(0xffffffffu, winc, off);
            if (lane >= off) winc += t;
        }
        wsum[lane] = winc - wv;
    }
    __syncthreads();
    int excl = blockOffset + wsum[wid] + incl - v;
    if (i < N_NODES) {
        g_row_ptr[i] = excl;
        g_cursor[i] = excl;
        g_nout[i] = rsqrtf(fmaxf((float)g_deg_out[i], 1.f));
        g_nin[i]  = rsqrtf(fmaxf((float)v, 1.f));
        if (i == N_NODES - 1) g_row_ptr[N_NODES] = excl + v;
    }
}

// ---------------- bucket fill with packed payload {src, nout(src)} ----------------
__global__ void fill_csr_kernel(const int* __restrict__ sbuf,
                                const int* __restrict__ dbuf) {
    int e = blockIdx.x * blockDim.x + threadIdx.x;
    if (e < N_EDGES) {
        int is64 = g_idx_is64;
        int s = is64 ? ((const int2*)sbuf)[e].x : sbuf[e];
        int d = is64 ? ((const int2*)dbuf)[e].x : dbuf[e];
        int pos = atomicAdd(&g_cursor[d], 1);
        g_csr_pack[pos] = make_int2(s, __float_as_int(g_nout[s]));
    }
}

// ---------------- fused CSR-gather + 3xTF32 mma GEMM (128 -> 128) ----------------
// Gather: each warp processes TWO rows (r, r+8) simultaneously -> 8 independent
// LDG.128 chains in flight. Payload int2 {src, nout} is one sequential 8B read.
template<int LAYER>
__global__ __launch_bounds__(256)
void fused_conv_kernel(const float* __restrict__ x,
                       const float* __restrict__ W,
                       const float* __restrict__ bias,
                       float* __restrict__ out) {
    extern __shared__ float smem[];
    float*  As_f = smem;                    // 64*132
    float4* As4  = (float4*)smem;           // rows stride 33 float4
    float*  Wt   = smem + 64 * 132;         // 128*133 (transposed W)
    float*  redS = Wt + 128 * 133;          // 4*128
    float*  redQ = redS + 512;              // 4*128

    int tid = threadIdx.x;
    int lane = tid & 31;
    int wid = tid >> 5;
    int rowBase = blockIdx.x * 64;
    const float4* x4 = (const float4*)x;

    // stage W transposed: Wt[n*133 + k] = W[k*128 + n]
    for (int i = tid; i < 128 * 128; i += 256) {
        int k = i >> 7, n = i & 127;
        Wt[n * 133 + k] = W[i];
    }

    float4 a4 = make_float4(0.f, 0.f, 0.f, 0.f);
    float4 c4 = make_float4(0.f, 0.f, 0.f, 0.f);
    if (LAYER == 2) {
        a4 = ((const float4*)g_bna)[lane];
        c4 = ((const float4*)g_bnb)[lane];
    }

    // gather phase: dual-row per warp
    for (int r0 = wid; r0 < 64; r0 += 16) {
        int rA = r0, rB = r0 + 8;
        int gA = rowBase + rA, gB = rowBase + rB;
        int jA = 0, eA = 0, jB = 0, eB = 0;
        if (gA < N_NODES) { jA = g_row_ptr[gA]; eA = g_row_ptr[gA + 1]; }
        if (gB < N_NODES) { jB = g_row_ptr[gB]; eB = g_row_ptr[gB + 1]; }
        float4 accA = make_float4(0.f, 0.f, 0.f, 0.f);
        float4 accB = make_float4(0.f, 0.f, 0.f, 0.f);

        // common interleaved quad loop: 8 independent float4 loads in flight
        while (jA + 4 <= eA && jB + 4 <= eB) {
            int2 pA[4], pB[4];
            #pragma unroll
            for (int u = 0; u < 4; u++) { pA[u] = g_csr_pack[jA + u]; pB[u] = g_csr_pack[jB + u]; }
            float4 vA[4], vB[4];
            #pragma unroll
            for (int u = 0; u < 4; u++) {
                vA[u] = x4[(size_t)pA[u].x * 32 + lane];
                vB[u] = x4[(size_t)pB[u].x * 32 + lane];
            }
            #pragma unroll
            for (int u = 0; u < 4; u++) {
                float nA = __int_as_float(pA[u].y);
                float nB = __int_as_float(pB[u].y);
                float4 wA = (LAYER == 2) ? bn_relu4(vA[u], a4, c4) : vA[u];
                float4 wB = (LAYER == 2) ? bn_relu4(vB[u], a4, c4) : vB[u];
                accA.x = fmaf(wA.x, nA, accA.x); accA.y = fmaf(wA.y, nA, accA.y);
                accA.z = fmaf(wA.z, nA, accA.z); accA.w = fmaf(wA.w, nA, accA.w);
                accB.x = fmaf(wB.x, nB, accB.x); accB.y = fmaf(wB.y, nB, accB.y);
                accB.z = fmaf(wB.z, nB, accB.z); accB.w = fmaf(wB.w, nB, accB.w);
            }
            jA += 4; jB += 4;
        }
        // drain A
        while (jA + 4 <= eA) {
            int2 p[4];
            #pragma unroll
            for (int u = 0; u < 4; u++) p[u] = g_csr_pack[jA + u];
            float4 v[4];
            #pragma unroll
            for (int u = 0; u < 4; u++) v[u] = x4[(size_t)p[u].x * 32 + lane];
            #pragma unroll
            for (int u = 0; u < 4; u++) {
                float n = __int_as_float(p[u].y);
                float4 w = (LAYER == 2) ? bn_relu4(v[u], a4, c4) : v[u];
                accA.x = fmaf(w.x, n, accA.x); accA.y = fmaf(w.y, n, accA.y);
                accA.z = fmaf(w.z, n, accA.z); accA.w = fmaf(w.w, n, accA.w);
            }
            jA += 4;
        }
        for (; jA < eA; jA++) {
            int2 p = g_csr_pack[jA];
            float n = __int_as_float(p.y);
            float4 v = x4[(size_t)p.x * 32 + lane];
            if (LAYER == 2) v = bn_relu4(v, a4, c4);
            accA.x = fmaf(v.x, n, accA.x); accA.y = fmaf(v.y, n, accA.y);
            accA.z = fmaf(v.z, n, accA.z); accA.w = fmaf(v.w, n, accA.w);
        }
        // drain B
        while (jB + 4 <= eB) {
            int2 p[4];
            #pragma unroll
            for (int u = 0; u < 4; u++) p[u] = g_csr_pack[jB + u];
            float4 v[4];
            #pragma unroll
            for (int u = 0; u < 4; u++) v[u] = x4[(size_t)p[u].x * 32 + lane];
            #pragma unroll
            for (int u = 0; u < 4; u++) {
                float n = __int_as_float(p[u].y);
                float4 w = (LAYER == 2) ? bn_relu4(v[u], a4, c4) : v[u];
                accB.x = fmaf(w.x, n, accB.x); accB.y = fmaf(w.y, n, accB.y);
                accB.z = fmaf(w.z, n, accB.z); accB.w = fmaf(w.w, n, accB.w);
            }
            jB += 4;
        }
        for (; jB < eB; jB++) {
            int2 p = g_csr_pack[jB];
            float n = __int_as_float(p.y);
            float4 v = x4[(size_t)p.x * 32 + lane];
            if (LAYER == 2) v = bn_relu4(v, a4, c4);
            accB.x = fmaf(v.x, n, accB.x); accB.y = fmaf(v.y, n, accB.y);
            accB.z = fmaf(v.z, n, accB.z); accB.w = fmaf(v.w, n, accB.w);
        }

        if (gA < N_NODES) {
            float ni = g_nin[gA];
            accA.x *= ni; accA.y *= ni; accA.z *= ni; accA.w *= ni;
        }
        if (gB < N_NODES) {
            float ni = g_nin[gB];
            accB.x *= ni; accB.y *= ni; accB.z *= ni; accB.w *= ni;
        }
        As4[rA * 33 + lane] = accA;
        As4[rB * 33 + lane] = accB;
    }
    __syncthreads();

    // mma phase: warp (warp_m 0..3, wn 0..1) computes m16 x n64, K=128
    int warp_m = wid & 3;
    int wn = wid >> 2;
    int qr = lane >> 2;       // 0..7
    int rr = lane & 3;        // 0..3
    int m0 = warp_m * 16 + qr;

    float c[8][4];
    #pragma unroll
    for (int nt = 0; nt < 8; nt++)
        #pragma unroll
        for (int q = 0; q < 4; q++) c[nt][q] = 0.f;

    #pragma unroll 2
    for (int ks = 0; ks < 16; ks++) {
        int k0 = ks * 8;
        float av0 = As_f[m0 * 132 + k0 + rr];
        float av1 = As_f[(m0 + 8) * 132 + k0 + rr];
        float av2 = As_f[m0 * 132 + k0 + 4 + rr];
        float av3 = As_f[(m0 + 8) * 132 + k0 + 4 + rr];
        uint32_t ah[4], al[4];
        ah[0] = f2tf(av0); al[0] = f2tf(av0 - __uint_as_float(ah[0]));
        ah[1] = f2tf(av1); al[1] = f2tf(av1 - __uint_as_float(ah[1]));
        ah[2] = f2tf(av2); al[2] = f2tf(av2 - __uint_as_float(ah[2]));
        ah[3] = f2tf(av3); al[3] = f2tf(av3 - __uint_as_float(ah[3]));
        #pragma unroll
        for (int nt = 0; nt < 8; nt++) {
            int nb = (wn * 64 + nt * 8 + qr) * 133 + k0 + rr;
            float b0 = Wt[nb];
            float b1 = Wt[nb + 4];
            uint32_t bh0 = f2tf(b0);
            uint32_t bh1 = f2tf(b1);
            uint32_t bl0 = __float_as_uint(b0 - __uint_as_float(bh0));
            uint32_t bl1 = __float_as_uint(b1 - __uint_as_float(bh1));
            mma_tf32(c[nt], ah, bh0, bh1);   // hi*hi
            mma_tf32(c[nt], al, bh0, bh1);   // lo*hi
            mma_tf32(c[nt], ah, bl0, bl1);   // hi*lo
        }
    }

    // epilogue: bias, store, BN stats
    int g0 = rowBase + m0;
    int g1 = g0 + 8;
    bool v0r = (g0 < N_NODES), v1r = (g1 < N_NODES);
    #pragma unroll
    for (int nt = 0; nt < 8; nt++) {
        int col = wn * 64 + nt * 8 + 2 * rr;
        float b0 = bias[col], b1 = bias[col + 1];
        float h00 = c[nt][0] + b0, h01 = c[nt][1] + b1;
        float h10 = c[nt][2] + b0, h11 = c[nt][3] + b1;
        if (v0r) *(float2*)&out[(size_t)g0 * 128 + col] = make_float2(h00, h01);
        if (v1r) *(float2*)&out[(size_t)g1 * 128 + col] = make_float2(h10, h11);
        float sA = (v0r ? h00 : 0.f) + (v1r ? h10 : 0.f);
        float sB = (v0r ? h01 : 0.f) + (v1r ? h11 : 0.f);
        float qA = (v0r ? h00 * h00 : 0.f) + (v1r ? h10 * h10 : 0.f);
        float qB = (v0r ? h01 * h01 : 0.f) + (v1r ? h11 * h11 : 0.f);
        #pragma unroll
        for (int off = 16; off >= 4; off >>= 1) {
            sA += __shfl_down_sync(0xffffffffu, sA, off);
            sB += __shfl_down_sync(0xffffffffu, sB, off);
            qA += __shfl_down_sync(0xffffffffu, qA, off);
            qB += __shfl_down_sync(0xffffffffu, qB, off);
        }
        if (lane < 4) {
            *(float2*)&redS[warp_m * 128 + col] = make_float2(sA, sB);
            *(float2*)&redQ[warp_m * 128 + col] = make_float2(qA, qB);
        }
    }
    __syncthreads();
    if (tid < 128) {
        float s = redS[tid] + redS[128 + tid] + redS[256 + tid] + redS[384 + tid];
        float q = redQ[tid] + redQ[128 + tid] + redQ[256 + tid] + redQ[384 + tid];
        atomicAdd(&g_sum[tid], s);
        atomicAdd(&g_sumsq[tid], q);
    }
}

// ---------------- layer-3 mma GEMM: y = relu(bn2(h2)) @ W3 * n_out ----------------
__global__ __launch_bounds__(256)
void mma_gemm64_kernel(const float* __restrict__ A,
                       const float* __restrict__ W,
                       float* __restrict__ out) {
    extern __shared__ float smem[];
    float*  As_f = smem;                    // 64*132
    float4* As4  = (float4*)smem;
    float*  Wt   = smem + 64 * 132;         // 64*133 (transposed W3)

    int tid = threadIdx.x;
    int rowBase = blockIdx.x * 64;

    for (int i = tid; i < 128 * 64; i += 256) {
        int k = i >> 6, n = i & 63;
        Wt[n * 133 + k] = W[i];
    }

    #pragma unroll
    for (int i = 0; i < 8; i++) {
        int slot = tid + i * 256;
        int lrow = slot >> 5;
        int kk = slot & 31;
        int grow = rowBase + lrow;
        float4 v = make_float4(0.f, 0.f, 0.f, 0.f);
        if (grow < N_NODES) {
            v = ((const float4*)A)[(size_t)grow * 32 + kk];
            float4 a4 = ((const float4*)g_bna)[kk];
            float4 b4 = ((const float4*)g_bnb)[kk];
            v = bn_relu4(v, a4, b4);
        }
        As4[lrow * 33 + kk] = v;
    }
    __syncthreads();

    int lane = tid & 31;
    int wid = tid >> 5;
    int warp_m = wid & 3;
    int wn = wid >> 2;
    int qr = lane >> 2;
    int rr = lane & 3;
    int m0 = warp_m * 16 + qr;

    float c[4][4];
    #pragma unroll
    for (int nt = 0; nt < 4; nt++)
        #pragma unroll
        for (int q = 0; q < 4; q++) c[nt][q] = 0.f;

    #pragma unroll 2
    for (int ks = 0; ks < 16; ks++) {
        int k0 = ks * 8;
        float av0 = As_f[m0 * 132 + k0 + rr];
        float av1 = As_f[(m0 + 8) * 132 + k0 + rr];
        float av2 = As_f[m0 * 132 + k0 + 4 + rr];
        float av3 = As_f[(m0 + 8) * 132 + k0 + 4 + rr];
        uint32_t ah[4], al[4];
        ah[0] = f2tf(av0); al[0] = f2tf(av0 - __uint_as_float(ah[0]));
        ah[1] = f2tf(av1); al[1] = f2tf(av1 - __uint_as_float(ah[1]));
        ah[2] = f2tf(av2); al[2] = f2tf(av2 - __uint_as_float(ah[2]));
        ah[3] = f2tf(av3); al[3] = f2tf(av3 - __uint_as_float(ah[3]));
        #pragma unroll
        for (int nt = 0; nt < 4; nt++) {
            int nb = (wn * 32 + nt * 8 + qr) * 133 + k0 + rr;
            float b0 = Wt[nb];
            float b1 = Wt[nb + 4];
            uint32_t bh0 = f2tf(b0);
            uint32_t bh1 = f2tf(b1);
            uint32_t bl0 = __float_as_uint(b0 - __uint_as_float(bh0));
            uint32_t bl1 = __float_as_uint(b1 - __uint_as_float(bh1));
            mma_tf32(c[nt], ah, bh0, bh1);
            mma_tf32(c[nt], al, bh0, bh1);
            mma_tf32(c[nt], ah, bl0, bl1);
        }
    }

    int g0 = rowBase + m0;
    int g1 = g0 + 8;
    float s0 = (g0 < N_NODES) ? g_nout[g0] : 0.f;
    float s1 = (g1 < N_NODES) ? g_nout[g1] : 0.f;
    #pragma unroll
    for (int nt = 0; nt < 4; nt++) {
        int col = wn * 32 + nt * 8 + 2 * rr;
        if (g0 < N_NODES)
            *(float2*)&out[(size_t)g0 * 64 + col] =
                make_float2(c[nt][0] * s0, c[nt][1] * s0);
        if (g1 < N_NODES)
            *(float2*)&out[(size_t)g1 * 64 + col] =
                make_float2(c[nt][2] * s1, c[nt][3] * s1);
    }
}

// ---------------- BN finalize ----------------
__global__ void bn_finalize_kernel(const float* __restrict__ gamma,
                                   const float* __restrict__ beta) {
    int t = threadIdx.x;
    if (t < F_HID) {
        float mean = g_sum[t] / (float)N_NODES;
        float var = g_sumsq[t] / (float)N_NODES - mean * mean;
        float a = gamma[t] * rsqrtf(var + BN_EPS);
        g_bna[t] = a;
        g_bnb[t] = fmaf(-mean, a, beta[t]);
        g_sum[t] = 0.f;
        g_sumsq[t] = 0.f;
    }
}

// ---------------- final CSR gather (64 feats), dual-node per warp ----------------
__global__ void gather64_kernel(const float* __restrict__ y,
                                const float* __restrict__ b3,
                                float* __restrict__ out) {
    int w = (blockIdx.x * blockDim.x + threadIdx.x) >> 5;
    int lane = threadIdx.x & 31;
    int nA = 2 * w, nB = 2 * w + 1;
    if (nA >= N_NODES) return;
    const float2* y2 = (const float2*)y;

    int jA = g_row_ptr[nA], eA = g_row_ptr[nA + 1];
    int jB = 0, eB = 0;
    if (nB < N_NODES) { jB = g_row_ptr[nB]; eB = g_row_ptr[nB + 1]; }
    float2 accA = make_float2(0.f, 0.f);
    float2 accB = make_float2(0.f, 0.f);

    while (jA + 4 <= eA && jB + 4 <= eB) {
        int sA[4], sB[4];
        #pragma unroll
        for (int u = 0; u < 4; u++) { sA[u] = g_csr_pack[jA + u].x; sB[u] = g_csr_pack[jB + u].x; }
        float2 vA[4], vB[4];
        #pragma unroll
        for (int u = 0; u < 4; u++) {
            vA[u] = y2[(size_t)sA[u] * 32 + lane];
            vB[u] = y2[(size_t)sB[u] * 32 + lane];
        }
        #pragma unroll
        for (int u = 0; u < 4; u++) {
            accA.x += vA[u].x; accA.y += vA[u].y;
            accB.x += vB[u].x; accB.y += vB[u].y;
        }
        jA += 4; jB += 4;
    }
    for (; jA < eA; jA++) {
        float2 v = y2[(size_t)g_csr_pack[jA].x * 32 + lane];
        accA.x += v.x; accA.y += v.y;
    }
    for (; jB < eB; jB++) {
        float2 v = y2[(size_t)g_csr_pack[jB].x * 32 + lane];
        accB.x += v.x; accB.y += v.y;
    }

    float2 b = ((const float2*)b3)[lane];
    float niA = g_nin[nA];
    ((float2*)out)[(size_t)nA * 32 + lane] =
        make_float2(fmaf(accA.x, niA, b.x), fmaf(accA.y, niA, b.y));
    if (nB < N_NODES) {
        float niB = g_nin[nB];
        ((float2*)out)[(size_t)nB * 32 + lane] =
            make_float2(fmaf(accB.x, niB, b.x), fmaf(accB.y, niB, b.y));
    }
}

// ---------------- host launcher ----------------
extern "C" void kernel_launch(void* const* d_in, const int* in_sizes, int n_in,
                              void* d_out, int out_size) {
    const float* features = (const float*)d_in[0];
    const int*   srcbuf   = (const int*)d_in[1];   // int32 or int64 (detected on device)
    const int*   dstbuf   = (const int*)d_in[2];
    const float* W1  = (const float*)d_in[3];
    const float* b1  = (const float*)d_in[4];
    const float* ga1 = (const float*)d_in[5];
    const float* be1 = (const float*)d_in[6];
    const float* W2  = (const float*)d_in[7];
    const float* b2  = (const float*)d_in[8];
    const float* ga2 = (const float*)d_in[9];
    const float* be2 = (const float*)d_in[10];
    const float* W3  = (const float*)d_in[11];
    const float* b3  = (const float*)d_in[12];
    float* out = (float*)d_out;

    void* p;
    cudaGetSymbolAddress(&p, g_h1);
    float* p_h1 = (float*)p;
    cudaGetSymbolAddress(&p, g_h2);
    float* p_h2 = (float*)p;
    void *p_do, *p_di, *p_sum, *p_sq;
    cudaGetSymbolAddress(&p_do, g_deg_out);
    cudaGetSymbolAddress(&p_di, g_deg_in);
    cudaGetSymbolAddress(&p_sum, g_sum);
    cudaGetSymbolAddress(&p_sq, g_sumsq);

    constexpr int SM_CONV = (64 * 132 + 128 * 133 + 1024) * 4;   // 105984
    constexpr int SM_G64  = (64 * 132 + 64 * 133) * 4;           // 67840

    cudaFuncSetAttribute(fused_conv_kernel<1>,
                         cudaFuncAttributeMaxDynamicSharedMemorySize, SM_CONV);
    cudaFuncSetAttribute(fused_conv_kernel<2>,
                         cudaFuncAttributeMaxDynamicSharedMemorySize, SM_CONV);
    cudaFuncSetAttribute(mma_gemm64_kernel,
                         cudaFuncAttributeMaxDynamicSharedMemorySize, SM_G64);

    int eblk = (N_EDGES + 255) / 256;
    int gblk = (N_NODES + 63) / 64;

    // graph preprocessing
    cudaMemsetAsync(p_do, 0, N_NODES * sizeof(int));
    cudaMemsetAsync(p_di, 0, N_NODES * sizeof(int));
    cudaMemsetAsync(p_sum, 0, F_HID * sizeof(float));
    cudaMemsetAsync(p_sq, 0, F_HID * sizeof(float));
    detect_kernel<<<1, 32>>>(srcbuf);
    degree_kernel<<<eblk, 256>>>(srcbuf, dstbuf);
    scanA_kernel<<<SCAN_BLOCKS, 1024>>>();
    scanB_kernel<<<SCAN_BLOCKS, 1024>>>();
    fill_csr_kernel<<<eblk, 256>>>(srcbuf, dstbuf);

    // ---- layer 1 ----
    fused_conv_kernel<1><<<gblk, 256, SM_CONV>>>(features, W1, b1, p_h1);
    bn_finalize_kernel<<<1, 128>>>(ga1, be1);

    // ---- layer 2 ----
    fused_conv_kernel<2><<<gblk, 256, SM_CONV>>>(p_h1, W2, b2, p_h2);
    bn_finalize_kernel<<<1, 128>>>(ga2, be2);

    // ---- layer 3: GEMM first (aggregation commutes with W3), then CSR gather ----
    mma_gemm64_kernel<<<gblk, 256, SM_G64>>>(p_h2, W3, p_h1);
    gather64_kernel<<<(N_NODES / 2 + 7) / 8, 256>>>(p_h1, b3, out);
}